// round 2
// baseline (speedup 1.0000x reference)
#include <cuda_runtime.h>
#include <cuda_bf16.h>
#include <cstdint>

#define BB 2
#define SS 4096
#define DD 512
#define HH 8
#define DK 64
#define BH (BB*HH)          // 16
#define MROWS (BB*SS)       // 8192

// Scratch (device globals: allocation-free)
__device__ float g_q[(size_t)BH * SS * DK];    // [B,H,S,DK] 16 MB
__device__ float g_k[(size_t)BH * SS * DK];
__device__ float g_v[(size_t)BH * SS * DK];
__device__ float g_ctx[(size_t)MROWS * DD];    // [B,S,D] 16 MB
__device__ float g_attn[(size_t)BH * SS * SS]; // 1 GiB (used only if attn not in d_out)

// ---------------------------------------------------------------------------
// GEMM: C[M x 512] = A[M x 512] @ W[512 x 512] + bias.
// headsplit=1 -> write to [B,H,S,DK] layout; else row-major [M,512].
// ---------------------------------------------------------------------------
__global__ __launch_bounds__(256) void gemm_bias_kernel(
    const float* __restrict__ A, const float* __restrict__ W,
    const float* __restrict__ bias, float* __restrict__ C, int headsplit)
{
    const int N = DD, Kd = DD;
    __shared__ float Ast[32][68]; // [k][m] transposed
    __shared__ float Bs[32][68];  // [k][n]
    int tid = threadIdx.x;
    int tx = tid & 15, ty = tid >> 4;
    int m0 = blockIdx.y * 64, n0 = blockIdx.x * 64;
    float acc[4][4] = {};
    for (int k0 = 0; k0 < Kd; k0 += 32) {
        #pragma unroll
        for (int l = tid; l < 512; l += 256) {
            int r  = l >> 3;          // 0..63 (A row)
            int kv = (l & 7) * 4;     // 0..28
            float4 a4 = *reinterpret_cast<const float4*>(&A[(size_t)(m0 + r) * Kd + k0 + kv]);
            Ast[kv + 0][r] = a4.x; Ast[kv + 1][r] = a4.y;
            Ast[kv + 2][r] = a4.z; Ast[kv + 3][r] = a4.w;
            int kr = l >> 4;          // 0..31 (W row)
            int nv = (l & 15) * 4;    // 0..60
            float4 b4 = *reinterpret_cast<const float4*>(&W[(size_t)(k0 + kr) * N + n0 + nv]);
            *reinterpret_cast<float4*>(&Bs[kr][nv]) = b4;
        }
        __syncthreads();
        #pragma unroll
        for (int kk = 0; kk < 32; kk++) {
            float4 a4 = *reinterpret_cast<float4*>(&Ast[kk][ty * 4]);
            float4 b4 = *reinterpret_cast<float4*>(&Bs[kk][tx * 4]);
            float a[4] = {a4.x, a4.y, a4.z, a4.w};
            float b[4] = {b4.x, b4.y, b4.z, b4.w};
            #pragma unroll
            for (int ii = 0; ii < 4; ii++)
                #pragma unroll
                for (int jj = 0; jj < 4; jj++)
                    acc[ii][jj] += a[ii] * b[jj];
        }
        __syncthreads();
    }
    #pragma unroll
    for (int ii = 0; ii < 4; ii++) {
        int m = m0 + ty * 4 + ii;
        #pragma unroll
        for (int jj = 0; jj < 4; jj++) {
            int n = n0 + tx * 4 + jj;
            float v = acc[ii][jj] + bias[n];
            if (headsplit) {
                int b = m >> 12, s = m & (SS - 1);
                int h = n >> 6, dk = n & 63;
                C[(((size_t)(b * HH + h)) * SS + s) * DK + dk] = v;
            } else {
                C[(size_t)m * DD + n] = v;
            }
        }
    }
}

// ---------------------------------------------------------------------------
// Scores: per (b,h), 64x64 tiles of q @ k^T * (1/8). Skips tiles above diagonal.
// ---------------------------------------------------------------------------
__global__ __launch_bounds__(256) void scores_kernel(
    const float* __restrict__ q, const float* __restrict__ k, float* __restrict__ attn)
{
    int bx = blockIdx.x;  // col tile (keys)
    int by = blockIdx.y;  // row tile (queries)
    if (bx > by) return;  // fully above diagonal
    int bh = blockIdx.z;
    const float* qb = q + (size_t)bh * SS * DK;
    const float* kb = k + (size_t)bh * SS * DK;
    float* ab = attn + (size_t)bh * SS * SS;

    __shared__ float Qs[DK][68]; // [d][row]
    __shared__ float Ks[DK][68]; // [d][col]
    int tid = threadIdx.x;
    #pragma unroll
    for (int l = tid; l < 1024; l += 256) {
        int r  = l >> 4;
        int dv = (l & 15) * 4;
        float4 a4 = *reinterpret_cast<const float4*>(&qb[(size_t)(by * 64 + r) * DK + dv]);
        Qs[dv + 0][r] = a4.x; Qs[dv + 1][r] = a4.y; Qs[dv + 2][r] = a4.z; Qs[dv + 3][r] = a4.w;
        float4 b4 = *reinterpret_cast<const float4*>(&kb[(size_t)(bx * 64 + r) * DK + dv]);
        Ks[dv + 0][r] = b4.x; Ks[dv + 1][r] = b4.y; Ks[dv + 2][r] = b4.z; Ks[dv + 3][r] = b4.w;
    }
    __syncthreads();
    int tx = tid & 15, ty = tid >> 4;
    float acc[4][4] = {};
    #pragma unroll
    for (int d = 0; d < DK; d++) {
        float4 a4 = *reinterpret_cast<float4*>(&Qs[d][ty * 4]);
        float4 b4 = *reinterpret_cast<float4*>(&Ks[d][tx * 4]);
        float a[4] = {a4.x, a4.y, a4.z, a4.w};
        float b[4] = {b4.x, b4.y, b4.z, b4.w};
        #pragma unroll
        for (int ii = 0; ii < 4; ii++)
            #pragma unroll
            for (int jj = 0; jj < 4; jj++)
                acc[ii][jj] += a[ii] * b[jj];
    }
    #pragma unroll
    for (int ii = 0; ii < 4; ii++) {
        int i = by * 64 + ty * 4 + ii;
        #pragma unroll
        for (int jj = 0; jj < 4; jj++) {
            int j = bx * 64 + tx * 4 + jj;
            ab[(size_t)i * SS + j] = acc[ii][jj] * 0.125f; // masked (j>i) overwritten by softmax
        }
    }
}

// ---------------------------------------------------------------------------
// Row softmax (causal): processes j in [0, i], writes zeros for j in (i, S).
// ---------------------------------------------------------------------------
__global__ __launch_bounds__(256) void softmax_kernel(float* __restrict__ attn)
{
    int i = blockIdx.x, bh = blockIdx.y;
    float* row = attn + (size_t)bh * SS * SS + (size_t)i * SS;
    __shared__ float buf[SS];
    __shared__ float red[8];
    int tid = threadIdx.x;
    int lane = tid & 31, wid = tid >> 5;
    int len = i + 1;

    float m = -3.0e38f;
    for (int j = tid; j < len; j += 256) { float x = row[j]; buf[j] = x; m = fmaxf(m, x); }
    #pragma unroll
    for (int o = 16; o; o >>= 1) m = fmaxf(m, __shfl_xor_sync(0xffffffffu, m, o));
    if (lane == 0) red[wid] = m;
    __syncthreads();
    m = red[0];
    #pragma unroll
    for (int w = 1; w < 8; w++) m = fmaxf(m, red[w]);

    float s = 0.f;
    for (int j = tid; j < len; j += 256) { float e = __expf(buf[j] - m); buf[j] = e; s += e; }
    #pragma unroll
    for (int o = 16; o; o >>= 1) s += __shfl_xor_sync(0xffffffffu, s, o);
    __syncthreads(); // protect red[] reuse
    if (lane == 0) red[wid] = s;
    __syncthreads();
    s = red[0];
    #pragma unroll
    for (int w = 1; w < 8; w++) s += red[w];
    float inv = 1.0f / s;

    for (int j = tid; j < len; j += 256) row[j] = buf[j] * inv;
    for (int j = len + tid; j < SS; j += 256) row[j] = 0.f;
}

// ---------------------------------------------------------------------------
// ctx = attn @ v (causal: only j-tiles <= row tile). Writes [B,S,D] layout.
// ---------------------------------------------------------------------------
__global__ __launch_bounds__(256) void ctx_kernel(
    const float* __restrict__ attn, const float* __restrict__ v, float* __restrict__ ctx)
{
    int by = blockIdx.x;  // row tile
    int bh = blockIdx.y;
    const float* ab = attn + (size_t)bh * SS * SS;
    const float* vb = v + (size_t)bh * SS * DK;
    __shared__ float Ats[64][68]; // [j][i]
    __shared__ float Vs[64][68];  // [j][dk]
    int tid = threadIdx.x;
    int tx = tid & 15, ty = tid >> 4;
    float acc[4][4] = {};
    for (int t = 0; t <= by; t++) {
        #pragma unroll
        for (int l = tid; l < 1024; l += 256) {
            int r  = l >> 4;
            int c4 = (l & 15) * 4;
            float4 a4 = *reinterpret_cast<const float4*>(&ab[(size_t)(by * 64 + r) * SS + t * 64 + c4]);
            Ats[c4 + 0][r] = a4.x; Ats[c4 + 1][r] = a4.y; Ats[c4 + 2][r] = a4.z; Ats[c4 + 3][r] = a4.w;
            float4 v4 = *reinterpret_cast<const float4*>(&vb[(size_t)(t * 64 + r) * DK + c4]);
            *reinterpret_cast<float4*>(&Vs[r][c4]) = v4;
        }
        __syncthreads();
        #pragma unroll
        for (int j = 0; j < 64; j++) {
            float4 a4 = *reinterpret_cast<float4*>(&Ats[j][ty * 4]);
            float4 b4 = *reinterpret_cast<float4*>(&Vs[j][tx * 4]);
            float a[4] = {a4.x, a4.y, a4.z, a4.w};
            float b[4] = {b4.x, b4.y, b4.z, b4.w};
            #pragma unroll
            for (int ii = 0; ii < 4; ii++)
                #pragma unroll
                for (int jj = 0; jj < 4; jj++)
                    acc[ii][jj] += a[ii] * b[jj];
        }
        __syncthreads();
    }
    int b = bh >> 3, h = bh & 7;
    #pragma unroll
    for (int ii = 0; ii < 4; ii++) {
        int i = by * 64 + ty * 4 + ii;
        #pragma unroll
        for (int jj = 0; jj < 4; jj++) {
            int dk = tx * 4 + jj;
            ctx[((size_t)(b * SS + i)) * DD + h * DK + dk] = acc[ii][jj];
        }
    }
}

// ---------------------------------------------------------------------------
extern "C" void kernel_launch(void* const* d_in, const int* in_sizes, int n_in,
                              void* d_out, int out_size)
{
    (void)in_sizes; (void)n_in;
    const float* Q  = (const float*)d_in[0];
    const float* K  = (const float*)d_in[1];
    const float* V  = (const float*)d_in[2];
    const float* wq = (const float*)d_in[3];
    const float* bq = (const float*)d_in[4];
    const float* wk = (const float*)d_in[5];
    const float* bk = (const float*)d_in[6];
    const float* wv = (const float*)d_in[7];
    const float* bv = (const float*)d_in[8];
    const float* wo = (const float*)d_in[9];
    const float* bo = (const float*)d_in[10];
    float* out = (float*)d_out;

    const size_t outN  = (size_t)MROWS * DD;               // 4,194,304
    const size_t attnN = (size_t)BH * SS * SS;             // 268,435,456

    float* attn;
    if ((size_t)out_size >= outN + attnN) {
        attn = out + outN;  // attn is part of the output tuple
    } else {
        void* p = nullptr;
        cudaGetSymbolAddress(&p, g_attn);
        attn = (float*)p;
    }

    float *qp, *kp, *vp, *ctxp;
    { void* p; cudaGetSymbolAddress(&p, g_q);   qp   = (float*)p; }
    { void* p; cudaGetSymbolAddress(&p, g_k);   kp   = (float*)p; }
    { void* p; cudaGetSymbolAddress(&p, g_v);   vp   = (float*)p; }
    { void* p; cudaGetSymbolAddress(&p, g_ctx); ctxp = (float*)p; }

    dim3 blk(256);
    dim3 gGemm(DD / 64, MROWS / 64);  // (8, 128)
    gemm_bias_kernel<<<gGemm, blk>>>(Q, wq, bq, qp, 1);
    gemm_bias_kernel<<<gGemm, blk>>>(K, wk, bk, kp, 1);
    gemm_bias_kernel<<<gGemm, blk>>>(V, wv, bv, vp, 1);

    dim3 gScore(SS / 64, SS / 64, BH);  // (64, 64, 16)
    scores_kernel<<<gScore, blk>>>(qp, kp, attn);

    dim3 gSoft(SS, BH);  // (4096, 16)
    softmax_kernel<<<gSoft, blk>>>(attn);

    dim3 gCtx(SS / 64, BH);  // (64, 16)
    ctx_kernel<<<gCtx, blk>>>(attn, vp, ctxp);

    gemm_bias_kernel<<<gGemm, blk>>>(ctxp, wo, bo, out, 0);
}

// round 3
// speedup vs baseline: 2.3384x; 2.3384x over previous
#include <cuda_runtime.h>
#include <cuda_bf16.h>
#include <cstdint>

#define BB 2
#define SS 4096
#define DD 512
#define HH 8
#define DK 64
#define BH (BB*HH)          // 16
#define MROWS (BB*SS)       // 8192

// Scratch (device globals: allocation-free)
__device__ float g_q[(size_t)BH * SS * DK];
__device__ float g_k[(size_t)BH * SS * DK];
__device__ float g_v[(size_t)BH * SS * DK];
__device__ float g_ctx[(size_t)MROWS * DD];
__device__ float g_attn[(size_t)BH * SS * SS]; // 1 GiB, used only if attn not in d_out

// ---------------------------------------------------------------------------
__device__ __forceinline__ uint32_t f2tf(float x) {
    uint32_t u;
    asm("cvt.rna.tf32.f32 %0, %1;" : "=r"(u) : "f"(x));
    return u;
}

__device__ __forceinline__ void mma8(float* d,
    uint32_t a0, uint32_t a1, uint32_t a2, uint32_t a3,
    uint32_t b0, uint32_t b1)
{
    asm volatile(
        "mma.sync.aligned.m16n8k8.row.col.f32.tf32.tf32.f32 "
        "{%0,%1,%2,%3},{%4,%5,%6,%7},{%8,%9},{%0,%1,%2,%3};"
        : "+f"(d[0]), "+f"(d[1]), "+f"(d[2]), "+f"(d[3])
        : "r"(a0), "r"(a1), "r"(a2), "r"(a3), "r"(b0), "r"(b1));
}

// ---------------------------------------------------------------------------
// Projection GEMM: C[M x 512] = A[M x 512] @ W[512 x 512] + bias (TF32 mma).
// Block tile 128x128, 8 warps (2m x 4n), warp tile 64x32, k-chunk 32.
// ---------------------------------------------------------------------------
__global__ __launch_bounds__(256) void gemm_tf32(
    const float* __restrict__ A, const float* __restrict__ W,
    const float* __restrict__ bias, float* __restrict__ C, int headsplit)
{
    __shared__ uint32_t As[128 * 36];   // row-major [m][k], ldk=36
    __shared__ uint32_t Bs[32 * 136];   // k-major  [k][n], ldn=136
    int tid = threadIdx.x;
    int lane = tid & 31, warp = tid >> 5;
    int wm = (warp >> 2) * 64, wn = (warp & 3) * 32;
    int r = lane >> 2, c = lane & 3;
    int m0 = blockIdx.y * 128, n0 = blockIdx.x * 128;

    float acc[4][4][4];
    #pragma unroll
    for (int im = 0; im < 4; im++)
        #pragma unroll
        for (int in = 0; in < 4; in++)
            #pragma unroll
            for (int q = 0; q < 4; q++) acc[im][in][q] = 0.f;

    for (int k0 = 0; k0 < DD; k0 += 32) {
        #pragma unroll
        for (int l = tid; l < 1024; l += 256) {
            int ar = l >> 3, ac4 = (l & 7) * 4;
            float4 av = *reinterpret_cast<const float4*>(&A[(size_t)(m0 + ar) * DD + k0 + ac4]);
            uint4 au = { f2tf(av.x), f2tf(av.y), f2tf(av.z), f2tf(av.w) };
            *reinterpret_cast<uint4*>(&As[ar * 36 + ac4]) = au;
            int kr = l >> 5, nv = (l & 31) * 4;
            float4 bv = *reinterpret_cast<const float4*>(&W[(size_t)(k0 + kr) * DD + n0 + nv]);
            uint4 bu = { f2tf(bv.x), f2tf(bv.y), f2tf(bv.z), f2tf(bv.w) };
            *reinterpret_cast<uint4*>(&Bs[kr * 136 + nv]) = bu;
        }
        __syncthreads();
        #pragma unroll
        for (int kk = 0; kk < 32; kk += 8) {
            uint32_t a[4][4], b[4][2];
            #pragma unroll
            for (int im = 0; im < 4; im++) {
                int mb = wm + im * 16;
                a[im][0] = As[(mb + r) * 36 + kk + c];
                a[im][1] = As[(mb + r + 8) * 36 + kk + c];
                a[im][2] = As[(mb + r) * 36 + kk + c + 4];
                a[im][3] = As[(mb + r + 8) * 36 + kk + c + 4];
            }
            #pragma unroll
            for (int in = 0; in < 4; in++) {
                int nb = wn + in * 8;
                b[in][0] = Bs[(kk + c) * 136 + nb + r];
                b[in][1] = Bs[(kk + c + 4) * 136 + nb + r];
            }
            #pragma unroll
            for (int im = 0; im < 4; im++)
                #pragma unroll
                for (int in = 0; in < 4; in++)
                    mma8(acc[im][in], a[im][0], a[im][1], a[im][2], a[im][3],
                         b[in][0], b[in][1]);
        }
        __syncthreads();
    }

    #pragma unroll
    for (int im = 0; im < 4; im++) {
        #pragma unroll
        for (int in = 0; in < 4; in++) {
            int row0 = m0 + wm + im * 16 + r;
            int col0 = n0 + wn + in * 8 + 2 * c;
            float bz0 = bias[col0], bz1 = bias[col0 + 1];
            #pragma unroll
            for (int half = 0; half < 2; half++) {
                int row = row0 + half * 8;
                float2 v;
                v.x = acc[im][in][half * 2 + 0] + bz0;
                v.y = acc[im][in][half * 2 + 1] + bz1;
                if (headsplit) {
                    int bb = row >> 12, s = row & (SS - 1);
                    int h = col0 >> 6, dk = col0 & 63;
                    *reinterpret_cast<float2*>(
                        &C[(((size_t)(bb * HH + h)) * SS + s) * DK + dk]) = v;
                } else {
                    *reinterpret_cast<float2*>(&C[(size_t)row * DD + col0]) = v;
                }
            }
        }
    }
}

// ---------------------------------------------------------------------------
// Scores: per (b,h), 128x128 tiles of q @ k^T * 0.125 (TF32 mma).
// Skips tiles fully above diagonal.
// ---------------------------------------------------------------------------
__global__ __launch_bounds__(256) void scores_tf32(
    const float* __restrict__ q, const float* __restrict__ k, float* __restrict__ attn)
{
    int bx = blockIdx.x, by = blockIdx.y;
    if (bx > by) return;
    int bh = blockIdx.z;
    const float* qb = q + (size_t)bh * SS * DK;
    const float* kb = k + (size_t)bh * SS * DK;
    float* ab = attn + (size_t)bh * SS * SS;

    __shared__ uint32_t Qs[128 * 36];  // row-major [m][d]
    __shared__ uint32_t Ks[128 * 36];  // row-major [n][d]
    int tid = threadIdx.x;
    int lane = tid & 31, warp = tid >> 5;
    int wm = (warp >> 2) * 64, wn = (warp & 3) * 32;
    int r = lane >> 2, c = lane & 3;

    float acc[4][4][4];
    #pragma unroll
    for (int im = 0; im < 4; im++)
        #pragma unroll
        for (int in = 0; in < 4; in++)
            #pragma unroll
            for (int qq = 0; qq < 4; qq++) acc[im][in][qq] = 0.f;

    for (int d0 = 0; d0 < DK; d0 += 32) {
        #pragma unroll
        for (int l = tid; l < 1024; l += 256) {
            int rr = l >> 3, dc4 = (l & 7) * 4;
            float4 qv = *reinterpret_cast<const float4*>(&qb[(size_t)(by * 128 + rr) * DK + d0 + dc4]);
            uint4 qu = { f2tf(qv.x), f2tf(qv.y), f2tf(qv.z), f2tf(qv.w) };
            *reinterpret_cast<uint4*>(&Qs[rr * 36 + dc4]) = qu;
            float4 kv = *reinterpret_cast<const float4*>(&kb[(size_t)(bx * 128 + rr) * DK + d0 + dc4]);
            uint4 ku = { f2tf(kv.x), f2tf(kv.y), f2tf(kv.z), f2tf(kv.w) };
            *reinterpret_cast<uint4*>(&Ks[rr * 36 + dc4]) = ku;
        }
        __syncthreads();
        #pragma unroll
        for (int kk = 0; kk < 32; kk += 8) {
            uint32_t a[4][4], b[4][2];
            #pragma unroll
            for (int im = 0; im < 4; im++) {
                int mb = wm + im * 16;
                a[im][0] = Qs[(mb + r) * 36 + kk + c];
                a[im][1] = Qs[(mb + r + 8) * 36 + kk + c];
                a[im][2] = Qs[(mb + r) * 36 + kk + c + 4];
                a[im][3] = Qs[(mb + r + 8) * 36 + kk + c + 4];
            }
            #pragma unroll
            for (int in = 0; in < 4; in++) {
                int nb = wn + in * 8;
                b[in][0] = Ks[(nb + r) * 36 + kk + c];
                b[in][1] = Ks[(nb + r) * 36 + kk + c + 4];
            }
            #pragma unroll
            for (int im = 0; im < 4; im++)
                #pragma unroll
                for (int in = 0; in < 4; in++)
                    mma8(acc[im][in], a[im][0], a[im][1], a[im][2], a[im][3],
                         b[in][0], b[in][1]);
        }
        __syncthreads();
    }

    #pragma unroll
    for (int im = 0; im < 4; im++) {
        #pragma unroll
        for (int in = 0; in < 4; in++) {
            int i0 = by * 128 + wm + im * 16 + r;
            int j0 = bx * 128 + wn + in * 8 + 2 * c;
            #pragma unroll
            for (int half = 0; half < 2; half++) {
                int i = i0 + half * 8;
                float2 v;
                v.x = acc[im][in][half * 2 + 0] * 0.125f;
                v.y = acc[im][in][half * 2 + 1] * 0.125f;
                *reinterpret_cast<float2*>(&ab[(size_t)i * SS + j0]) = v;
            }
        }
    }
}

// ---------------------------------------------------------------------------
// Row softmax (causal), register-resident, float4 I/O.
// Writes zeros for j>i in the same pass.
// ---------------------------------------------------------------------------
__global__ __launch_bounds__(256) void softmax_v(float* __restrict__ attn)
{
    int i = blockIdx.x, bh = blockIdx.y;
    float* row = attn + (size_t)bh * SS * SS + (size_t)i * SS;
    int tid = threadIdx.x;
    int lane = tid & 31, wid = tid >> 5;
    __shared__ float red[8];

    float4 x[4];
    float m = -3.0e38f;
    #pragma unroll
    for (int it = 0; it < 4; it++) {
        int j4 = (tid + it * 256) * 4;
        float4 v;
        if (j4 + 3 <= i) {
            v = *reinterpret_cast<const float4*>(&row[j4]);
        } else {
            v.x = (j4 + 0 <= i) ? row[j4 + 0] : -3.0e38f;
            v.y = (j4 + 1 <= i) ? row[j4 + 1] : -3.0e38f;
            v.z = (j4 + 2 <= i) ? row[j4 + 2] : -3.0e38f;
            v.w = (j4 + 3 <= i) ? row[j4 + 3] : -3.0e38f;
        }
        x[it] = v;
        m = fmaxf(m, fmaxf(fmaxf(v.x, v.y), fmaxf(v.z, v.w)));
    }
    #pragma unroll
    for (int o = 16; o; o >>= 1) m = fmaxf(m, __shfl_xor_sync(0xffffffffu, m, o));
    if (lane == 0) red[wid] = m;
    __syncthreads();
    m = red[0];
    #pragma unroll
    for (int w = 1; w < 8; w++) m = fmaxf(m, red[w]);

    float s = 0.f;
    #pragma unroll
    for (int it = 0; it < 4; it++) {
        int j4 = (tid + it * 256) * 4;
        float4 v = x[it];
        v.x = (j4 + 0 <= i) ? __expf(v.x - m) : 0.f;
        v.y = (j4 + 1 <= i) ? __expf(v.y - m) : 0.f;
        v.z = (j4 + 2 <= i) ? __expf(v.z - m) : 0.f;
        v.w = (j4 + 3 <= i) ? __expf(v.w - m) : 0.f;
        x[it] = v;
        s += v.x + v.y + v.z + v.w;
    }
    #pragma unroll
    for (int o = 16; o; o >>= 1) s += __shfl_xor_sync(0xffffffffu, s, o);
    __syncthreads();  // protect red[] reuse
    if (lane == 0) red[wid] = s;
    __syncthreads();
    s = red[0];
    #pragma unroll
    for (int w = 1; w < 8; w++) s += red[w];
    float inv = 1.0f / s;

    #pragma unroll
    for (int it = 0; it < 4; it++) {
        int j4 = (tid + it * 256) * 4;
        float4 v = x[it];
        v.x *= inv; v.y *= inv; v.z *= inv; v.w *= inv;
        *reinterpret_cast<float4*>(&row[j4]) = v;
    }
}

// ---------------------------------------------------------------------------
// ctx = attn @ v (TF32 mma). Block tile 128 rows x 64 (DK) cols.
// 8 warps (4m x 2n), warp tile 32x32. Causal: k-chunks only up to row tile end.
// ---------------------------------------------------------------------------
__global__ __launch_bounds__(256) void ctx_tf32(
    const float* __restrict__ attn, const float* __restrict__ v, float* __restrict__ ctx)
{
    int by = gridDim.x - 1 - blockIdx.x;  // biggest tiles first
    int bh = blockIdx.y;
    const float* ab = attn + (size_t)bh * SS * SS;
    const float* vb = v + (size_t)bh * SS * DK;

    __shared__ uint32_t As[128 * 36];  // row-major [m][j-chunk]
    __shared__ uint32_t Vs[32 * 72];   // k-major  [j][dk], ldn=72
    int tid = threadIdx.x;
    int lane = tid & 31, warp = tid >> 5;
    int wm = (warp >> 1) * 32, wn = (warp & 1) * 32;
    int r = lane >> 2, c = lane & 3;

    float acc[2][4][4];
    #pragma unroll
    for (int im = 0; im < 2; im++)
        #pragma unroll
        for (int in = 0; in < 4; in++)
            #pragma unroll
            for (int qq = 0; qq < 4; qq++) acc[im][in][qq] = 0.f;

    int nchunks = (by + 1) * 4;
    for (int t = 0; t < nchunks; t++) {
        int k0 = t * 32;
        #pragma unroll
        for (int l = tid; l < 1024; l += 256) {
            int ar = l >> 3, jc4 = (l & 7) * 4;
            float4 av = *reinterpret_cast<const float4*>(&ab[(size_t)(by * 128 + ar) * SS + k0 + jc4]);
            uint4 au = { f2tf(av.x), f2tf(av.y), f2tf(av.z), f2tf(av.w) };
            *reinterpret_cast<uint4*>(&As[ar * 36 + jc4]) = au;
        }
        #pragma unroll
        for (int l = tid; l < 512; l += 256) {
            int jr = l >> 4, dv = (l & 15) * 4;
            float4 vv = *reinterpret_cast<const float4*>(&vb[(size_t)(k0 + jr) * DK + dv]);
            uint4 vu = { f2tf(vv.x), f2tf(vv.y), f2tf(vv.z), f2tf(vv.w) };
            *reinterpret_cast<uint4*>(&Vs[jr * 72 + dv]) = vu;
        }
        __syncthreads();
        #pragma unroll
        for (int kk = 0; kk < 32; kk += 8) {
            uint32_t a[2][4], b[4][2];
            #pragma unroll
            for (int im = 0; im < 2; im++) {
                int mb = wm + im * 16;
                a[im][0] = As[(mb + r) * 36 + kk + c];
                a[im][1] = As[(mb + r + 8) * 36 + kk + c];
                a[im][2] = As[(mb + r) * 36 + kk + c + 4];
                a[im][3] = As[(mb + r + 8) * 36 + kk + c + 4];
            }
            #pragma unroll
            for (int in = 0; in < 4; in++) {
                int nb = wn + in * 8;
                b[in][0] = Vs[(kk + c) * 72 + nb + r];
                b[in][1] = Vs[(kk + c + 4) * 72 + nb + r];
            }
            #pragma unroll
            for (int im = 0; im < 2; im++)
                #pragma unroll
                for (int in = 0; in < 4; in++)
                    mma8(acc[im][in], a[im][0], a[im][1], a[im][2], a[im][3],
                         b[in][0], b[in][1]);
        }
        __syncthreads();
    }

    int bb = bh >> 3, h = bh & 7;
    #pragma unroll
    for (int im = 0; im < 2; im++) {
        #pragma unroll
        for (int in = 0; in < 4; in++) {
            int i0 = by * 128 + wm + im * 16 + r;
            int dk0 = wn + in * 8 + 2 * c;
            #pragma unroll
            for (int half = 0; half < 2; half++) {
                int i = i0 + half * 8;
                float2 vv;
                vv.x = acc[im][in][half * 2 + 0];
                vv.y = acc[im][in][half * 2 + 1];
                *reinterpret_cast<float2*>(
                    &ctx[((size_t)(bb * SS + i)) * DD + h * DK + dk0]) = vv;
            }
        }
    }
}

// ---------------------------------------------------------------------------
extern "C" void kernel_launch(void* const* d_in, const int* in_sizes, int n_in,
                              void* d_out, int out_size)
{
    (void)in_sizes; (void)n_in;
    const float* Q  = (const float*)d_in[0];
    const float* K  = (const float*)d_in[1];
    const float* V  = (const float*)d_in[2];
    const float* wq = (const float*)d_in[3];
    const float* bq = (const float*)d_in[4];
    const float* wk = (const float*)d_in[5];
    const float* bk = (const float*)d_in[6];
    const float* wv = (const float*)d_in[7];
    const float* bv = (const float*)d_in[8];
    const float* wo = (const float*)d_in[9];
    const float* bo = (const float*)d_in[10];
    float* out = (float*)d_out;

    const size_t outN  = (size_t)MROWS * DD;
    const size_t attnN = (size_t)BH * SS * SS;

    float* attn;
    if ((size_t)out_size >= outN + attnN) {
        attn = out + outN;
    } else {
        void* p = nullptr;
        cudaGetSymbolAddress(&p, g_attn);
        attn = (float*)p;
    }

    float *qp, *kp, *vp, *ctxp;
    { void* p; cudaGetSymbolAddress(&p, g_q);   qp   = (float*)p; }
    { void* p; cudaGetSymbolAddress(&p, g_k);   kp   = (float*)p; }
    { void* p; cudaGetSymbolAddress(&p, g_v);   vp   = (float*)p; }
    { void* p; cudaGetSymbolAddress(&p, g_ctx); ctxp = (float*)p; }

    dim3 blk(256);
    dim3 gGemm(DD / 128, MROWS / 128);  // (4, 64)
    gemm_tf32<<<gGemm, blk>>>(Q, wq, bq, qp, 1);
    gemm_tf32<<<gGemm, blk>>>(K, wk, bk, kp, 1);
    gemm_tf32<<<gGemm, blk>>>(V, wv, bv, vp, 1);

    dim3 gScore(SS / 128, SS / 128, BH);  // (32, 32, 16)
    scores_tf32<<<gScore, blk>>>(qp, kp, attn);

    dim3 gSoft(SS, BH);  // (4096, 16)
    softmax_v<<<gSoft, blk>>>(attn);

    dim3 gCtx(SS / 128, BH);  // (32, 16)
    ctx_tf32<<<gCtx, blk>>>(attn, vp, ctxp);

    gemm_tf32<<<gGemm, blk>>>(ctxp, wo, bo, out, 0);
}

// round 4
// speedup vs baseline: 2.4136x; 1.0322x over previous
#include <cuda_runtime.h>
#include <cuda_bf16.h>
#include <cstdint>

#define BB 2
#define SS 4096
#define DD 512
#define HH 8
#define DK 64
#define BH (BB*HH)          // 16
#define MROWS (BB*SS)       // 8192

// Scratch (device globals: allocation-free)
__device__ float g_q[(size_t)BH * SS * DK];
__device__ float g_k[(size_t)BH * SS * DK];
__device__ float g_v[(size_t)BH * SS * DK];
__device__ float g_ctx[(size_t)MROWS * DD];
__device__ float g_attn[(size_t)BH * SS * SS]; // 1 GiB, used only if attn not in d_out

// ---------------------------------------------------------------------------
__device__ __forceinline__ uint32_t f2tf(float x) {
    uint32_t u;
    asm("cvt.rna.tf32.f32 %0, %1;" : "=r"(u) : "f"(x));
    return u;
}

__device__ __forceinline__ void mma8(float* d,
    uint32_t a0, uint32_t a1, uint32_t a2, uint32_t a3,
    uint32_t b0, uint32_t b1)
{
    asm volatile(
        "mma.sync.aligned.m16n8k8.row.col.f32.tf32.tf32.f32 "
        "{%0,%1,%2,%3},{%4,%5,%6,%7},{%8,%9},{%0,%1,%2,%3};"
        : "+f"(d[0]), "+f"(d[1]), "+f"(d[2]), "+f"(d[3])
        : "r"(a0), "r"(a1), "r"(a2), "r"(a3), "r"(b0), "r"(b1));
}

// ---------------------------------------------------------------------------
// Projection GEMM: C[M x 512] = A[M x 512] @ W[512 x 512] + bias (TF32 mma).
// ---------------------------------------------------------------------------
__global__ __launch_bounds__(256) void gemm_tf32(
    const float* __restrict__ A, const float* __restrict__ W,
    const float* __restrict__ bias, float* __restrict__ C, int headsplit)
{
    __shared__ uint32_t As[128 * 36];   // row-major [m][k], ldk=36
    __shared__ uint32_t Bs[32 * 136];   // k-major  [k][n], ldn=136
    int tid = threadIdx.x;
    int lane = tid & 31, warp = tid >> 5;
    int wm = (warp >> 2) * 64, wn = (warp & 3) * 32;
    int r = lane >> 2, c = lane & 3;
    int m0 = blockIdx.y * 128, n0 = blockIdx.x * 128;

    float acc[4][4][4];
    #pragma unroll
    for (int im = 0; im < 4; im++)
        #pragma unroll
        for (int in = 0; in < 4; in++)
            #pragma unroll
            for (int q = 0; q < 4; q++) acc[im][in][q] = 0.f;

    for (int k0 = 0; k0 < DD; k0 += 32) {
        #pragma unroll
        for (int l = tid; l < 1024; l += 256) {
            int ar = l >> 3, ac4 = (l & 7) * 4;
            float4 av = *reinterpret_cast<const float4*>(&A[(size_t)(m0 + ar) * DD + k0 + ac4]);
            uint4 au = { f2tf(av.x), f2tf(av.y), f2tf(av.z), f2tf(av.w) };
            *reinterpret_cast<uint4*>(&As[ar * 36 + ac4]) = au;
            int kr = l >> 5, nv = (l & 31) * 4;
            float4 bv = *reinterpret_cast<const float4*>(&W[(size_t)(k0 + kr) * DD + n0 + nv]);
            uint4 bu = { f2tf(bv.x), f2tf(bv.y), f2tf(bv.z), f2tf(bv.w) };
            *reinterpret_cast<uint4*>(&Bs[kr * 136 + nv]) = bu;
        }
        __syncthreads();
        #pragma unroll
        for (int kk = 0; kk < 32; kk += 8) {
            uint32_t a[4][4], b[4][2];
            #pragma unroll
            for (int im = 0; im < 4; im++) {
                int mb = wm + im * 16;
                a[im][0] = As[(mb + r) * 36 + kk + c];
                a[im][1] = As[(mb + r + 8) * 36 + kk + c];
                a[im][2] = As[(mb + r) * 36 + kk + c + 4];
                a[im][3] = As[(mb + r + 8) * 36 + kk + c + 4];
            }
            #pragma unroll
            for (int in = 0; in < 4; in++) {
                int nb = wn + in * 8;
                b[in][0] = Bs[(kk + c) * 136 + nb + r];
                b[in][1] = Bs[(kk + c + 4) * 136 + nb + r];
            }
            #pragma unroll
            for (int im = 0; im < 4; im++)
                #pragma unroll
                for (int in = 0; in < 4; in++)
                    mma8(acc[im][in], a[im][0], a[im][1], a[im][2], a[im][3],
                         b[in][0], b[in][1]);
        }
        __syncthreads();
    }

    #pragma unroll
    for (int im = 0; im < 4; im++) {
        #pragma unroll
        for (int in = 0; in < 4; in++) {
            int row0 = m0 + wm + im * 16 + r;
            int col0 = n0 + wn + in * 8 + 2 * c;
            float bz0 = bias[col0], bz1 = bias[col0 + 1];
            #pragma unroll
            for (int half = 0; half < 2; half++) {
                int row = row0 + half * 8;
                float2 v;
                v.x = acc[im][in][half * 2 + 0] + bz0;
                v.y = acc[im][in][half * 2 + 1] + bz1;
                if (headsplit) {
                    int bb = row >> 12, s = row & (SS - 1);
                    int h = col0 >> 6, dk = col0 & 63;
                    *reinterpret_cast<float2*>(
                        &C[(((size_t)(bb * HH + h)) * SS + s) * DK + dk]) = v;
                } else {
                    *reinterpret_cast<float2*>(&C[(size_t)row * DD + col0]) = v;
                }
            }
        }
    }
}

// ---------------------------------------------------------------------------
// Fused causal attention: per (b,h) 128-query tile.
// Pass A: online softmax stats (m, l) over k-tiles of 64 keys.
// Pass B: recompute S, P = exp(s-m)/l, optional attn write, O += P @ V.
// 8 warps, each owns 16 query rows. Dynamic smem:
//   Qs [128][68] tf32 | Ks [64][68] | Vs [64][72] k-major | Ps per-warp [16][68]
// ---------------------------------------------------------------------------
#define FA_SMEM_WORDS (8704 + 4352 + 4608 + 8 * 1088)   // 26368
#define FA_SMEM_BYTES (FA_SMEM_WORDS * 4)               // 105472

__global__ __launch_bounds__(256, 2) void fused_attn(
    const float* __restrict__ q, const float* __restrict__ k,
    const float* __restrict__ v, float* __restrict__ attn,
    float* __restrict__ ctx, int write_attn)
{
    extern __shared__ uint32_t smem[];
    uint32_t* Qs = smem;                  // 128*68
    uint32_t* Ks = smem + 8704;           // 64*68
    uint32_t* Vs = smem + 13056;          // 64*72
    int tid = threadIdx.x;
    int lane = tid & 31, wq = tid >> 5;
    int r = lane >> 2, c = lane & 3;
    uint32_t* Ps = smem + 17664 + wq * 1088;  // per-warp 16*68

    int by = (int)gridDim.x - 1 - (int)blockIdx.x;  // biggest workloads first
    int bh = blockIdx.y;
    const float* qb = q + (size_t)bh * SS * DK;
    const float* kb = k + (size_t)bh * SS * DK;
    const float* vb = v + (size_t)bh * SS * DK;
    float* ab = attn + (size_t)bh * SS * SS;

    int ktmax = 2 * by + 1;
    int ibase = by * 128 + wq * 16;
    int i0 = ibase + r, i1 = i0 + 8;

    // ---- load Q tile once ----
    #pragma unroll 4
    for (int l = tid; l < 2048; l += 256) {
        int rr = l >> 4, c4 = (l & 15) * 4;
        float4 qv = *reinterpret_cast<const float4*>(&qb[(size_t)(by * 128 + rr) * DK + c4]);
        uint4 qu = { f2tf(qv.x), f2tf(qv.y), f2tf(qv.z), f2tf(qv.w) };
        *reinterpret_cast<uint4*>(&Qs[rr * 68 + c4]) = qu;
    }

    float m0 = -1e30f, m1 = -1e30f, l0 = 0.f, l1 = 0.f;

    // ================= PASS A: softmax stats =================
    for (int kt = 0; kt <= ktmax; kt++) {
        __syncthreads();
        #pragma unroll 4
        for (int l = tid; l < 1024; l += 256) {
            int rr = l >> 4, c4 = (l & 15) * 4;
            float4 kv = *reinterpret_cast<const float4*>(&kb[(size_t)(kt * 64 + rr) * DK + c4]);
            uint4 ku = { f2tf(kv.x), f2tf(kv.y), f2tf(kv.z), f2tf(kv.w) };
            *reinterpret_cast<uint4*>(&Ks[rr * 68 + c4]) = ku;
        }
        __syncthreads();

        float s[8][4];
        #pragma unroll
        for (int n = 0; n < 8; n++)
            #pragma unroll
            for (int qq = 0; qq < 4; qq++) s[n][qq] = 0.f;
        const uint32_t* qrow = Qs + (size_t)(wq * 16) * 68;
        #pragma unroll
        for (int kk = 0; kk < 64; kk += 8) {
            uint32_t a0 = qrow[r * 68 + kk + c];
            uint32_t a1 = qrow[(r + 8) * 68 + kk + c];
            uint32_t a2 = qrow[r * 68 + kk + c + 4];
            uint32_t a3 = qrow[(r + 8) * 68 + kk + c + 4];
            #pragma unroll
            for (int n = 0; n < 8; n++) {
                uint32_t b0 = Ks[(n * 8 + r) * 68 + kk + c];
                uint32_t b1 = Ks[(n * 8 + r) * 68 + kk + c + 4];
                mma8(s[n], a0, a1, a2, a3, b0, b1);
            }
        }

        bool diag = (kt >= 2 * by);
        float mx0 = -1e30f, mx1 = -1e30f;
        #pragma unroll
        for (int n = 0; n < 8; n++) {
            int j0 = kt * 64 + n * 8 + 2 * c;
            float v0 = s[n][0] * 0.125f, v1 = s[n][1] * 0.125f;
            float v2 = s[n][2] * 0.125f, v3 = s[n][3] * 0.125f;
            if (diag) {
                if (j0     > i0) v0 = -1e30f;
                if (j0 + 1 > i0) v1 = -1e30f;
                if (j0     > i1) v2 = -1e30f;
                if (j0 + 1 > i1) v3 = -1e30f;
            }
            s[n][0] = v0; s[n][1] = v1; s[n][2] = v2; s[n][3] = v3;
            mx0 = fmaxf(mx0, fmaxf(v0, v1));
            mx1 = fmaxf(mx1, fmaxf(v2, v3));
        }
        mx0 = fmaxf(mx0, __shfl_xor_sync(0xffffffffu, mx0, 1));
        mx0 = fmaxf(mx0, __shfl_xor_sync(0xffffffffu, mx0, 2));
        mx1 = fmaxf(mx1, __shfl_xor_sync(0xffffffffu, mx1, 1));
        mx1 = fmaxf(mx1, __shfl_xor_sync(0xffffffffu, mx1, 2));
        float mn0 = fmaxf(m0, mx0), mn1 = fmaxf(m1, mx1);
        float sum0 = 0.f, sum1 = 0.f;
        #pragma unroll
        for (int n = 0; n < 8; n++) {
            sum0 += __expf(s[n][0] - mn0) + __expf(s[n][1] - mn0);
            sum1 += __expf(s[n][2] - mn1) + __expf(s[n][3] - mn1);
        }
        sum0 += __shfl_xor_sync(0xffffffffu, sum0, 1);
        sum0 += __shfl_xor_sync(0xffffffffu, sum0, 2);
        sum1 += __shfl_xor_sync(0xffffffffu, sum1, 1);
        sum1 += __shfl_xor_sync(0xffffffffu, sum1, 2);
        l0 = l0 * __expf(m0 - mn0) + sum0; m0 = mn0;
        l1 = l1 * __expf(m1 - mn1) + sum1; m1 = mn1;
    }

    float inv0 = 1.0f / l0, inv1 = 1.0f / l1;

    // ================= PASS B: P write + P @ V =================
    float o[8][4];
    #pragma unroll
    for (int n = 0; n < 8; n++)
        #pragma unroll
        for (int qq = 0; qq < 4; qq++) o[n][qq] = 0.f;

    for (int kt = 0; kt <= ktmax; kt++) {
        __syncthreads();
        #pragma unroll 4
        for (int l = tid; l < 1024; l += 256) {
            int rr = l >> 4, c4 = (l & 15) * 4;
            float4 kv = *reinterpret_cast<const float4*>(&kb[(size_t)(kt * 64 + rr) * DK + c4]);
            uint4 ku = { f2tf(kv.x), f2tf(kv.y), f2tf(kv.z), f2tf(kv.w) };
            *reinterpret_cast<uint4*>(&Ks[rr * 68 + c4]) = ku;
            float4 vv = *reinterpret_cast<const float4*>(&vb[(size_t)(kt * 64 + rr) * DK + c4]);
            uint4 vu = { f2tf(vv.x), f2tf(vv.y), f2tf(vv.z), f2tf(vv.w) };
            *reinterpret_cast<uint4*>(&Vs[rr * 72 + c4]) = vu;
        }
        __syncthreads();

        float s[8][4];
        #pragma unroll
        for (int n = 0; n < 8; n++)
            #pragma unroll
            for (int qq = 0; qq < 4; qq++) s[n][qq] = 0.f;
        const uint32_t* qrow = Qs + (size_t)(wq * 16) * 68;
        #pragma unroll
        for (int kk = 0; kk < 64; kk += 8) {
            uint32_t a0 = qrow[r * 68 + kk + c];
            uint32_t a1 = qrow[(r + 8) * 68 + kk + c];
            uint32_t a2 = qrow[r * 68 + kk + c + 4];
            uint32_t a3 = qrow[(r + 8) * 68 + kk + c + 4];
            #pragma unroll
            for (int n = 0; n < 8; n++) {
                uint32_t b0 = Ks[(n * 8 + r) * 68 + kk + c];
                uint32_t b1 = Ks[(n * 8 + r) * 68 + kk + c + 4];
                mma8(s[n], a0, a1, a2, a3, b0, b1);
            }
        }

        bool diag = (kt >= 2 * by);
        #pragma unroll
        for (int n = 0; n < 8; n++) {
            int j0 = kt * 64 + n * 8 + 2 * c;
            float v0 = s[n][0] * 0.125f, v1 = s[n][1] * 0.125f;
            float v2 = s[n][2] * 0.125f, v3 = s[n][3] * 0.125f;
            if (diag) {
                if (j0     > i0) v0 = -1e30f;
                if (j0 + 1 > i0) v1 = -1e30f;
                if (j0     > i1) v2 = -1e30f;
                if (j0 + 1 > i1) v3 = -1e30f;
            }
            float p0 = __expf(v0 - m0) * inv0;
            float p1 = __expf(v1 - m0) * inv0;
            float p2 = __expf(v2 - m1) * inv1;
            float p3 = __expf(v3 - m1) * inv1;
            if (write_attn) {
                float2 w01 = { p0, p1 };
                float2 w23 = { p2, p3 };
                *reinterpret_cast<float2*>(&ab[(size_t)i0 * SS + j0]) = w01;
                *reinterpret_cast<float2*>(&ab[(size_t)i1 * SS + j0]) = w23;
            }
            int pc = n * 8 + 2 * c;
            Ps[r * 68 + pc]           = f2tf(p0);
            Ps[r * 68 + pc + 1]       = f2tf(p1);
            Ps[(r + 8) * 68 + pc]     = f2tf(p2);
            Ps[(r + 8) * 68 + pc + 1] = f2tf(p3);
        }
        __syncwarp();

        #pragma unroll
        for (int kk = 0; kk < 64; kk += 8) {
            uint32_t a0 = Ps[r * 68 + kk + c];
            uint32_t a1 = Ps[(r + 8) * 68 + kk + c];
            uint32_t a2 = Ps[r * 68 + kk + c + 4];
            uint32_t a3 = Ps[(r + 8) * 68 + kk + c + 4];
            #pragma unroll
            for (int n = 0; n < 8; n++) {
                uint32_t b0 = Vs[(kk + c) * 72 + n * 8 + r];
                uint32_t b1 = Vs[(kk + c + 4) * 72 + n * 8 + r];
                mma8(o[n], a0, a1, a2, a3, b0, b1);
            }
        }
    }

    // ---- write O to ctx [B,S,D] ----
    int bb = bh >> 3, h = bh & 7;
    #pragma unroll
    for (int n = 0; n < 8; n++) {
        int dk = n * 8 + 2 * c;
        float2 w0 = { o[n][0], o[n][1] };
        float2 w1 = { o[n][2], o[n][3] };
        *reinterpret_cast<float2*>(&ctx[((size_t)(bb * SS + i0)) * DD + h * 64 + dk]) = w0;
        *reinterpret_cast<float2*>(&ctx[((size_t)(bb * SS + i1)) * DD + h * 64 + dk]) = w1;
    }

    // ---- zero-fill upper region of attn (j beyond processed tiles) ----
    if (write_attn) {
        int c0 = (ktmax + 1) * 64;
        int nf4 = (SS - c0) >> 2;
        if (nf4 > 0) {
            float4 z = { 0.f, 0.f, 0.f, 0.f };
            for (int rr = 0; rr < 128; rr++) {
                float* rowp = &ab[(size_t)(by * 128 + rr) * SS + c0];
                for (int cc = tid; cc < nf4; cc += 256)
                    *reinterpret_cast<float4*>(&rowp[cc * 4]) = z;
            }
        }
    }
}

// ---------------------------------------------------------------------------
extern "C" void kernel_launch(void* const* d_in, const int* in_sizes, int n_in,
                              void* d_out, int out_size)
{
    (void)in_sizes; (void)n_in;
    const float* Q  = (const float*)d_in[0];
    const float* K  = (const float*)d_in[1];
    const float* V  = (const float*)d_in[2];
    const float* wq = (const float*)d_in[3];
    const float* bq = (const float*)d_in[4];
    const float* wk = (const float*)d_in[5];
    const float* bk = (const float*)d_in[6];
    const float* wv = (const float*)d_in[7];
    const float* bv = (const float*)d_in[8];
    const float* wo = (const float*)d_in[9];
    const float* bo = (const float*)d_in[10];
    float* out = (float*)d_out;

    const size_t outN  = (size_t)MROWS * DD;
    const size_t attnN = (size_t)BH * SS * SS;

    int write_attn;
    float* attn;
    if ((size_t)out_size >= outN + attnN) {
        attn = out + outN;
        write_attn = 1;
    } else {
        void* p = nullptr;
        cudaGetSymbolAddress(&p, g_attn);
        attn = (float*)p;
        write_attn = 0;   // nothing reads attn in the fused path
    }

    float *qp, *kp, *vp, *ctxp;
    { void* p; cudaGetSymbolAddress(&p, g_q);   qp   = (float*)p; }
    { void* p; cudaGetSymbolAddress(&p, g_k);   kp   = (float*)p; }
    { void* p; cudaGetSymbolAddress(&p, g_v);   vp   = (float*)p; }
    { void* p; cudaGetSymbolAddress(&p, g_ctx); ctxp = (float*)p; }

    cudaFuncSetAttribute(fused_attn, cudaFuncAttributeMaxDynamicSharedMemorySize,
                         FA_SMEM_BYTES);

    dim3 blk(256);
    dim3 gGemm(DD / 128, MROWS / 128);  // (4, 64)
    gemm_tf32<<<gGemm, blk>>>(Q, wq, bq, qp, 1);
    gemm_tf32<<<gGemm, blk>>>(K, wk, bk, kp, 1);
    gemm_tf32<<<gGemm, blk>>>(V, wv, bv, vp, 1);

    dim3 gFA(SS / 128, BH);  // (32, 16)
    fused_attn<<<gFA, blk, FA_SMEM_BYTES>>>(qp, kp, vp, attn, ctxp, write_attn);

    gemm_tf32<<<gGemm, blk>>>(ctxp, wo, bo, out, 0);
}

// round 6
// speedup vs baseline: 2.5416x; 1.0530x over previous
#include <cuda_runtime.h>
#include <cuda_bf16.h>
#include <cstdint>

#define BB 2
#define SS 4096
#define DD 512
#define HH 8
#define DK 64
#define BH (BB*HH)          // 16
#define MROWS (BB*SS)       // 8192

// log2(e) * 0.125 (softmax scale folded into base-2 domain)
#define SCL 0.18033688011112042f

// Scratch (device globals: allocation-free)
__device__ float g_q[(size_t)BH * SS * DK];
__device__ float g_k[(size_t)BH * SS * DK];
__device__ float g_v[(size_t)BH * SS * DK];
__device__ float g_ctx[(size_t)MROWS * DD];
__device__ float g_m[(size_t)BH * SS];
__device__ float g_linv[(size_t)BH * SS];
__device__ float g_attn[(size_t)BH * SS * SS]; // used only if attn not in d_out

// ---------------------------------------------------------------------------
__device__ __forceinline__ uint32_t f2tf(float x) {
    uint32_t u;
    asm("cvt.rna.tf32.f32 %0, %1;" : "=r"(u) : "f"(x));
    return u;
}
__device__ __forceinline__ float tfr(float x) {       // tf32-rounded float
    return __uint_as_float(f2tf(x));
}
__device__ __forceinline__ float ex2(float x) {
    float y;
    asm("ex2.approx.ftz.f32 %0, %1;" : "=f"(y) : "f"(x));
    return y;
}

__device__ __forceinline__ void mma8(float* d,
    uint32_t a0, uint32_t a1, uint32_t a2, uint32_t a3,
    uint32_t b0, uint32_t b1)
{
    asm volatile(
        "mma.sync.aligned.m16n8k8.row.col.f32.tf32.tf32.f32 "
        "{%0,%1,%2,%3},{%4,%5,%6,%7},{%8,%9},{%0,%1,%2,%3};"
        : "+f"(d[0]), "+f"(d[1]), "+f"(d[2]), "+f"(d[3])
        : "r"(a0), "r"(a1), "r"(a2), "r"(a3), "r"(b0), "r"(b1));
}

// ---------------------------------------------------------------------------
// GEMM core (TF32 mma): C[M x 512] = A[M x 512] @ W[512 x 512] + bias.
// round_split=1 -> tf32-round outputs and write [B,H,S,DK]; else plain [M,512].
// ---------------------------------------------------------------------------
__device__ __forceinline__ void gemm_body(
    const float* __restrict__ A, const float* __restrict__ W,
    const float* __restrict__ bias, float* __restrict__ C,
    int round_split, uint32_t* As, uint32_t* Bs)
{
    int tid = threadIdx.x;
    int lane = tid & 31, warp = tid >> 5;
    int wm = (warp >> 2) * 64, wn = (warp & 3) * 32;
    int r = lane >> 2, c = lane & 3;
    int m0 = blockIdx.y * 128, n0 = blockIdx.x * 128;

    float acc[4][4][4];
    #pragma unroll
    for (int im = 0; im < 4; im++)
        #pragma unroll
        for (int in = 0; in < 4; in++)
            #pragma unroll
            for (int q = 0; q < 4; q++) acc[im][in][q] = 0.f;

    for (int k0 = 0; k0 < DD; k0 += 32) {
        #pragma unroll
        for (int l = tid; l < 1024; l += 256) {
            int ar = l >> 3, ac4 = (l & 7) * 4;
            float4 av = *reinterpret_cast<const float4*>(&A[(size_t)(m0 + ar) * DD + k0 + ac4]);
            uint4 au = { f2tf(av.x), f2tf(av.y), f2tf(av.z), f2tf(av.w) };
            *reinterpret_cast<uint4*>(&As[ar * 36 + ac4]) = au;
            int kr = l >> 5, nv = (l & 31) * 4;
            float4 bv = *reinterpret_cast<const float4*>(&W[(size_t)(k0 + kr) * DD + n0 + nv]);
            uint4 bu = { f2tf(bv.x), f2tf(bv.y), f2tf(bv.z), f2tf(bv.w) };
            *reinterpret_cast<uint4*>(&Bs[kr * 136 + nv]) = bu;
        }
        __syncthreads();
        #pragma unroll
        for (int kk = 0; kk < 32; kk += 8) {
            uint32_t a[4][4], b[4][2];
            #pragma unroll
            for (int im = 0; im < 4; im++) {
                int mb = wm + im * 16;
                a[im][0] = As[(mb + r) * 36 + kk + c];
                a[im][1] = As[(mb + r + 8) * 36 + kk + c];
                a[im][2] = As[(mb + r) * 36 + kk + c + 4];
                a[im][3] = As[(mb + r + 8) * 36 + kk + c + 4];
            }
            #pragma unroll
            for (int in = 0; in < 4; in++) {
                int nb = wn + in * 8;
                b[in][0] = Bs[(kk + c) * 136 + nb + r];
                b[in][1] = Bs[(kk + c + 4) * 136 + nb + r];
            }
            #pragma unroll
            for (int im = 0; im < 4; im++)
                #pragma unroll
                for (int in = 0; in < 4; in++)
                    mma8(acc[im][in], a[im][0], a[im][1], a[im][2], a[im][3],
                         b[in][0], b[in][1]);
        }
        __syncthreads();
    }

    #pragma unroll
    for (int im = 0; im < 4; im++) {
        #pragma unroll
        for (int in = 0; in < 4; in++) {
            int row0 = m0 + wm + im * 16 + r;
            int col0 = n0 + wn + in * 8 + 2 * c;
            float bz0 = bias[col0], bz1 = bias[col0 + 1];
            #pragma unroll
            for (int half = 0; half < 2; half++) {
                int row = row0 + half * 8;
                float2 v;
                v.x = acc[im][in][half * 2 + 0] + bz0;
                v.y = acc[im][in][half * 2 + 1] + bz1;
                if (round_split) {
                    v.x = tfr(v.x); v.y = tfr(v.y);
                    int bb = row >> 12, s = row & (SS - 1);
                    int h = col0 >> 6, dk = col0 & 63;
                    *reinterpret_cast<float2*>(
                        &C[(((size_t)(bb * HH + h)) * SS + s) * DK + dk]) = v;
                } else {
                    *reinterpret_cast<float2*>(&C[(size_t)row * DD + col0]) = v;
                }
            }
        }
    }
}

// Fused Q/K/V projection: blockIdx.z selects which projection.
__global__ __launch_bounds__(256) void gemm_qkv(
    const float* __restrict__ Q, const float* __restrict__ K, const float* __restrict__ V,
    const float* __restrict__ wq, const float* __restrict__ wk, const float* __restrict__ wv,
    const float* __restrict__ bq, const float* __restrict__ bk, const float* __restrict__ bv,
    float* __restrict__ cq, float* __restrict__ ck, float* __restrict__ cv)
{
    __shared__ uint32_t As[128 * 36];
    __shared__ uint32_t Bs[32 * 136];
    const float *A, *W, *bias; float* C;
    if (blockIdx.z == 0)      { A = Q; W = wq; bias = bq; C = cq; }
    else if (blockIdx.z == 1) { A = K; W = wk; bias = bk; C = ck; }
    else                      { A = V; W = wv; bias = bv; C = cv; }
    gemm_body(A, W, bias, C, 1, As, Bs);
}

__global__ __launch_bounds__(256) void gemm_out(
    const float* __restrict__ A, const float* __restrict__ W,
    const float* __restrict__ bias, float* __restrict__ C)
{
    __shared__ uint32_t As[128 * 36];
    __shared__ uint32_t Bs[32 * 136];
    gemm_body(A, W, bias, C, 0, As, Bs);
}

// ---------------------------------------------------------------------------
// Single-pass flash attention (causal). Per (b,h) 128-query tile, k-tiles of 64.
// Online softmax in base-2 domain; writes ctx and per-row (m, 1/l) stats.
// smem: Qs[128][68] | Ks[64][68] | Vs[64][72] | Ps per-warp [16][68]
// ---------------------------------------------------------------------------
#define FL_SMEM_WORDS (8704 + 4352 + 4608 + 8 * 1088)   // 26368
#define FL_SMEM_BYTES (FL_SMEM_WORDS * 4)               // 105472

__global__ __launch_bounds__(256, 2) void flash_attn(
    const float* __restrict__ q, const float* __restrict__ k,
    const float* __restrict__ v, float* __restrict__ ctx,
    float* __restrict__ gm, float* __restrict__ glinv)
{
    extern __shared__ uint32_t smem[];
    uint32_t* Qs = smem;                  // 128*68
    uint32_t* Ks = smem + 8704;           // 64*68
    uint32_t* Vs = smem + 13056;          // 64*72
    int tid = threadIdx.x;
    int lane = tid & 31, wq = tid >> 5;
    int r = lane >> 2, c = lane & 3;
    uint32_t* Ps = smem + 17664 + wq * 1088;  // per-warp 16*68

    int by = (int)gridDim.x - 1 - (int)blockIdx.x;  // biggest workloads first
    int bh = blockIdx.y;
    const float* qb = q + (size_t)bh * SS * DK;
    const float* kb = k + (size_t)bh * SS * DK;
    const float* vb = v + (size_t)bh * SS * DK;

    int ktmax = 2 * by + 1;
    int ibase = by * 128 + wq * 16;
    int i0 = ibase + r, i1 = i0 + 8;

    // Q tile: pre-rounded tf32 floats -> straight bit copy
    #pragma unroll 4
    for (int l = tid; l < 2048; l += 256) {
        int rr = l >> 4, c4 = (l & 15) * 4;
        *reinterpret_cast<uint4*>(&Qs[rr * 68 + c4]) =
            *reinterpret_cast<const uint4*>(&qb[(size_t)(by * 128 + rr) * DK + c4]);
    }

    float m0 = -1e30f, m1 = -1e30f, l0 = 0.f, l1 = 0.f;
    float o[8][4];
    #pragma unroll
    for (int n = 0; n < 8; n++)
        #pragma unroll
        for (int qq = 0; qq < 4; qq++) o[n][qq] = 0.f;

    for (int kt = 0; kt <= ktmax; kt++) {
        __syncthreads();
        #pragma unroll 4
        for (int l = tid; l < 1024; l += 256) {
            int rr = l >> 4, c4 = (l & 15) * 4;
            *reinterpret_cast<uint4*>(&Ks[rr * 68 + c4]) =
                *reinterpret_cast<const uint4*>(&kb[(size_t)(kt * 64 + rr) * DK + c4]);
            *reinterpret_cast<uint4*>(&Vs[rr * 72 + c4]) =
                *reinterpret_cast<const uint4*>(&vb[(size_t)(kt * 64 + rr) * DK + c4]);
        }
        __syncthreads();

        // S = Q K^T
        float s[8][4];
        #pragma unroll
        for (int n = 0; n < 8; n++)
            #pragma unroll
            for (int qq = 0; qq < 4; qq++) s[n][qq] = 0.f;
        const uint32_t* qrow = Qs + (size_t)(wq * 16) * 68;
        #pragma unroll
        for (int kk = 0; kk < 64; kk += 8) {
            uint32_t a0 = qrow[r * 68 + kk + c];
            uint32_t a1 = qrow[(r + 8) * 68 + kk + c];
            uint32_t a2 = qrow[r * 68 + kk + c + 4];
            uint32_t a3 = qrow[(r + 8) * 68 + kk + c + 4];
            #pragma unroll
            for (int n = 0; n < 8; n++) {
                uint32_t b0 = Ks[(n * 8 + r) * 68 + kk + c];
                uint32_t b1 = Ks[(n * 8 + r) * 68 + kk + c + 4];
                mma8(s[n], a0, a1, a2, a3, b0, b1);
            }
        }

        // scale to log2 domain + causal mask + row max
        bool diag = (kt >= 2 * by);
        float mx0 = -1e30f, mx1 = -1e30f;
        #pragma unroll
        for (int n = 0; n < 8; n++) {
            int j0 = kt * 64 + n * 8 + 2 * c;
            float t0 = s[n][0] * SCL, t1 = s[n][1] * SCL;
            float t2 = s[n][2] * SCL, t3 = s[n][3] * SCL;
            if (diag) {
                if (j0     > i0) t0 = -1e30f;
                if (j0 + 1 > i0) t1 = -1e30f;
                if (j0     > i1) t2 = -1e30f;
                if (j0 + 1 > i1) t3 = -1e30f;
            }
            s[n][0] = t0; s[n][1] = t1; s[n][2] = t2; s[n][3] = t3;
            mx0 = fmaxf(mx0, fmaxf(t0, t1));
            mx1 = fmaxf(mx1, fmaxf(t2, t3));
        }
        mx0 = fmaxf(mx0, __shfl_xor_sync(0xffffffffu, mx0, 1));
        mx0 = fmaxf(mx0, __shfl_xor_sync(0xffffffffu, mx0, 2));
        mx1 = fmaxf(mx1, __shfl_xor_sync(0xffffffffu, mx1, 1));
        mx1 = fmaxf(mx1, __shfl_xor_sync(0xffffffffu, mx1, 2));
        float mn0 = fmaxf(m0, mx0), mn1 = fmaxf(m1, mx1);
        float f0 = ex2(m0 - mn0), f1 = ex2(m1 - mn1);

        float sum0 = 0.f, sum1 = 0.f;
        #pragma unroll
        for (int n = 0; n < 8; n++) {
            float p0 = ex2(s[n][0] - mn0);
            float p1 = ex2(s[n][1] - mn0);
            float p2 = ex2(s[n][2] - mn1);
            float p3 = ex2(s[n][3] - mn1);
            sum0 += p0 + p1; sum1 += p2 + p3;
            int pc = n * 8 + 2 * c;
            Ps[r * 68 + pc]           = f2tf(p0);
            Ps[r * 68 + pc + 1]       = f2tf(p1);
            Ps[(r + 8) * 68 + pc]     = f2tf(p2);
            Ps[(r + 8) * 68 + pc + 1] = f2tf(p3);
        }
        sum0 += __shfl_xor_sync(0xffffffffu, sum0, 1);
        sum0 += __shfl_xor_sync(0xffffffffu, sum0, 2);
        sum1 += __shfl_xor_sync(0xffffffffu, sum1, 1);
        sum1 += __shfl_xor_sync(0xffffffffu, sum1, 2);
        l0 = l0 * f0 + sum0; m0 = mn0;
        l1 = l1 * f1 + sum1; m1 = mn1;

        // rescale O
        #pragma unroll
        for (int n = 0; n < 8; n++) {
            o[n][0] *= f0; o[n][1] *= f0;
            o[n][2] *= f1; o[n][3] *= f1;
        }
        __syncwarp();

        // O += P V
        #pragma unroll
        for (int kk = 0; kk < 64; kk += 8) {
            uint32_t a0 = Ps[r * 68 + kk + c];
            uint32_t a1 = Ps[(r + 8) * 68 + kk + c];
            uint32_t a2 = Ps[r * 68 + kk + c + 4];
            uint32_t a3 = Ps[(r + 8) * 68 + kk + c + 4];
            #pragma unroll
            for (int n = 0; n < 8; n++) {
                uint32_t b0 = Vs[(kk + c) * 72 + n * 8 + r];
                uint32_t b1 = Vs[(kk + c + 4) * 72 + n * 8 + r];
                mma8(o[n], a0, a1, a2, a3, b0, b1);
            }
        }
    }

    float inv0 = 1.0f / l0, inv1 = 1.0f / l1;

    // per-row stats for the attn-writer
    if (c == 0) {
        gm[(size_t)bh * SS + i0] = m0;  glinv[(size_t)bh * SS + i0] = inv0;
        gm[(size_t)bh * SS + i1] = m1;  glinv[(size_t)bh * SS + i1] = inv1;
    }

    // write O to ctx [B,S,D]
    int bb = bh >> 3, h = bh & 7;
    #pragma unroll
    for (int n = 0; n < 8; n++) {
        int dk = n * 8 + 2 * c;
        float2 w0 = { o[n][0] * inv0, o[n][1] * inv0 };
        float2 w1 = { o[n][2] * inv1, o[n][3] * inv1 };
        *reinterpret_cast<float2*>(&ctx[((size_t)(bb * SS + i0)) * DD + h * 64 + dk]) = w0;
        *reinterpret_cast<float2*>(&ctx[((size_t)(bb * SS + i1)) * DD + h * 64 + dk]) = w1;
    }
}

// ---------------------------------------------------------------------------
// attn writer: recompute S = Q K^T per 128x128 tile, p = ex2(t-m)*linv.
// Tiles above the diagonal are pure zero-fill. Streaming stores.
// smem: Qs[128][68] | Ks[128][68]
// ---------------------------------------------------------------------------
#define AW_SMEM_WORDS (8704 * 2)            // 17408
#define AW_SMEM_BYTES (AW_SMEM_WORDS * 4)   // 69632

__global__ __launch_bounds__(256, 2) void attn_write(
    const float* __restrict__ q, const float* __restrict__ k,
    const float* __restrict__ gm, const float* __restrict__ glinv,
    float* __restrict__ attn)
{
    int bx = blockIdx.x, by = blockIdx.y, bh = blockIdx.z;
    float* ab = attn + (size_t)bh * SS * SS;
    int tid = threadIdx.x;

    if (bx > by) {  // zero tile
        float4 z = { 0.f, 0.f, 0.f, 0.f };
        #pragma unroll 4
        for (int l = tid; l < 4096; l += 256) {
            int rr = l >> 5, c4 = (l & 31) * 4;
            __stcs(reinterpret_cast<float4*>(
                &ab[(size_t)(by * 128 + rr) * SS + bx * 128 + c4]), z);
        }
        return;
    }

    extern __shared__ uint32_t sm2[];
    uint32_t* Qs = sm2;           // 128*68
    uint32_t* Ks = sm2 + 8704;    // 128*68
    const float* qb = q + (size_t)bh * SS * DK;
    const float* kb = k + (size_t)bh * SS * DK;

    #pragma unroll 4
    for (int l = tid; l < 2048; l += 256) {
        int rr = l >> 4, c4 = (l & 15) * 4;
        *reinterpret_cast<uint4*>(&Qs[rr * 68 + c4]) =
            *reinterpret_cast<const uint4*>(&qb[(size_t)(by * 128 + rr) * DK + c4]);
        *reinterpret_cast<uint4*>(&Ks[rr * 68 + c4]) =
            *reinterpret_cast<const uint4*>(&kb[(size_t)(bx * 128 + rr) * DK + c4]);
    }
    __syncthreads();

    int lane = tid & 31, warp = tid >> 5;
    int wm = (warp >> 2) * 64, wn = (warp & 3) * 32;
    int r = lane >> 2, c = lane & 3;

    float acc[4][4][4];
    #pragma unroll
    for (int im = 0; im < 4; im++)
        #pragma unroll
        for (int in = 0; in < 4; in++)
            #pragma unroll
            for (int qq = 0; qq < 4; qq++) acc[im][in][qq] = 0.f;

    #pragma unroll
    for (int kk = 0; kk < 64; kk += 8) {
        uint32_t a[4][4], b[4][2];
        #pragma unroll
        for (int im = 0; im < 4; im++) {
            int mb = wm + im * 16;
            a[im][0] = Qs[(mb + r) * 68 + kk + c];
            a[im][1] = Qs[(mb + r + 8) * 68 + kk + c];
            a[im][2] = Qs[(mb + r) * 68 + kk + c + 4];
            a[im][3] = Qs[(mb + r + 8) * 68 + kk + c + 4];
        }
        #pragma unroll
        for (int in = 0; in < 4; in++) {
            int nb = wn + in * 8;
            b[in][0] = Ks[(nb + r) * 68 + kk + c];
            b[in][1] = Ks[(nb + r) * 68 + kk + c + 4];
        }
        #pragma unroll
        for (int im = 0; im < 4; im++)
            #pragma unroll
            for (int in = 0; in < 4; in++)
                mma8(acc[im][in], a[im][0], a[im][1], a[im][2], a[im][3],
                     b[in][0], b[in][1]);
    }

    bool dg = (bx == by);
    #pragma unroll
    for (int im = 0; im < 4; im++) {
        int i0 = by * 128 + wm + im * 16 + r;
        int i1 = i0 + 8;
        float m_0 = gm[(size_t)bh * SS + i0], li0 = glinv[(size_t)bh * SS + i0];
        float m_1 = gm[(size_t)bh * SS + i1], li1 = glinv[(size_t)bh * SS + i1];
        #pragma unroll
        for (int in = 0; in < 4; in++) {
            int j0 = bx * 128 + wn + in * 8 + 2 * c;
            float p0 = ex2(acc[im][in][0] * SCL - m_0) * li0;
            float p1 = ex2(acc[im][in][1] * SCL - m_0) * li0;
            float p2 = ex2(acc[im][in][2] * SCL - m_1) * li1;
            float p3 = ex2(acc[im][in][3] * SCL - m_1) * li1;
            if (dg) {
                if (j0     > i0) p0 = 0.f;
                if (j0 + 1 > i0) p1 = 0.f;
                if (j0     > i1) p2 = 0.f;
                if (j0 + 1 > i1) p3 = 0.f;
            }
            float2 w01 = { p0, p1 };
            float2 w23 = { p2, p3 };
            __stcs(reinterpret_cast<float2*>(&ab[(size_t)i0 * SS + j0]), w01);
            __stcs(reinterpret_cast<float2*>(&ab[(size_t)i1 * SS + j0]), w23);
        }
    }
}

// ---------------------------------------------------------------------------
extern "C" void kernel_launch(void* const* d_in, const int* in_sizes, int n_in,
                              void* d_out, int out_size)
{
    (void)in_sizes; (void)n_in;
    const float* Q  = (const float*)d_in[0];
    const float* K  = (const float*)d_in[1];
    const float* V  = (const float*)d_in[2];
    const float* wq = (const float*)d_in[3];
    const float* bq = (const float*)d_in[4];
    const float* wk = (const float*)d_in[5];
    const float* bk = (const float*)d_in[6];
    const float* wv = (const float*)d_in[7];
    const float* bv = (const float*)d_in[8];
    const float* wo = (const float*)d_in[9];
    const float* bo = (const float*)d_in[10];
    float* out = (float*)d_out;

    const size_t outN  = (size_t)MROWS * DD;
    const size_t attnN = (size_t)BH * SS * SS;

    int write_attn;
    float* attn;
    if ((size_t)out_size >= outN + attnN) {
        attn = out + outN;
        write_attn = 1;
    } else {
        void* p = nullptr;
        cudaGetSymbolAddress(&p, g_attn);
        attn = (float*)p;
        write_attn = 0;
    }

    float *qp, *kp, *vp, *ctxp, *mp, *lp;
    { void* p; cudaGetSymbolAddress(&p, g_q);    qp   = (float*)p; }
    { void* p; cudaGetSymbolAddress(&p, g_k);    kp   = (float*)p; }
    { void* p; cudaGetSymbolAddress(&p, g_v);    vp   = (float*)p; }
    { void* p; cudaGetSymbolAddress(&p, g_ctx);  ctxp = (float*)p; }
    { void* p; cudaGetSymbolAddress(&p, g_m);    mp   = (float*)p; }
    { void* p; cudaGetSymbolAddress(&p, g_linv); lp   = (float*)p; }

    cudaFuncSetAttribute(flash_attn, cudaFuncAttributeMaxDynamicSharedMemorySize,
                         FL_SMEM_BYTES);
    cudaFuncSetAttribute(attn_write, cudaFuncAttributeMaxDynamicSharedMemorySize,
                         AW_SMEM_BYTES);

    dim3 blk(256);

    // fused Q/K/V projections (pre-rounded tf32 outputs, [B,H,S,DK] layout)
    dim3 gQKV(DD / 128, MROWS / 128, 3);   // (4, 64, 3) = 768 blocks
    gemm_qkv<<<gQKV, blk>>>(Q, K, V, wq, wk, wv, bq, bk, bv, qp, kp, vp);

    // single-pass flash attention -> ctx + (m, 1/l)
    dim3 gFA(SS / 128, BH);  // (32, 16)
    flash_attn<<<gFA, blk, FL_SMEM_BYTES>>>(qp, kp, vp, ctxp, mp, lp);

    // output projection (independent of attn writing)
    dim3 gOut(DD / 128, MROWS / 128);  // (4, 64)
    gemm_out<<<gOut, blk>>>(ctxp, wo, bo, out);

    // attn tensor materialization
    if (write_attn) {
        dim3 gAW(SS / 128, SS / 128, BH);  // (32, 32, 16)
        attn_write<<<gAW, blk, AW_SMEM_BYTES>>>(qp, kp, mp, lp, attn);
    }
}

// round 7
// speedup vs baseline: 2.9642x; 1.1663x over previous
#include <cuda_runtime.h>
#include <cuda_bf16.h>
#include <cstdint>

#define BB 2
#define SS 4096
#define DD 512
#define HH 8
#define DK 64
#define BH (BB*HH)          // 16
#define MROWS (BB*SS)       // 8192

// log2(e) * 0.125 (softmax scale folded into base-2 domain)
#define SCL 0.18033688011112042f

// Scratch (device globals: allocation-free)
__device__ float g_q[(size_t)BH * SS * DK];
__device__ float g_k[(size_t)BH * SS * DK];
__device__ float g_v[(size_t)BH * SS * DK];
__device__ float g_ctx[(size_t)MROWS * DD];
__device__ float g_m[(size_t)BH * SS];
__device__ float g_linv[(size_t)BH * SS];
__device__ float g_opart[(size_t)BH * 32 * 4 * 128 * DK];   // 67 MB partial O
__device__ float g_mpart[(size_t)BH * 32 * 4 * 128];
__device__ float g_lpart[(size_t)BH * 32 * 4 * 128];
__device__ float g_attn[(size_t)BH * SS * SS]; // used only if attn not in d_out

// ---------------------------------------------------------------------------
__device__ __forceinline__ uint32_t f2tf(float x) {
    uint32_t u;
    asm("cvt.rna.tf32.f32 %0, %1;" : "=r"(u) : "f"(x));
    return u;
}
__device__ __forceinline__ float tfr(float x) {
    return __uint_as_float(f2tf(x));
}
__device__ __forceinline__ float ex2(float x) {
    float y;
    asm("ex2.approx.ftz.f32 %0, %1;" : "=f"(y) : "f"(x));
    return y;
}
__device__ __forceinline__ void mma8(float* d,
    uint32_t a0, uint32_t a1, uint32_t a2, uint32_t a3,
    uint32_t b0, uint32_t b1)
{
    asm volatile(
        "mma.sync.aligned.m16n8k8.row.col.f32.tf32.tf32.f32 "
        "{%0,%1,%2,%3},{%4,%5,%6,%7},{%8,%9},{%0,%1,%2,%3};"
        : "+f"(d[0]), "+f"(d[1]), "+f"(d[2]), "+f"(d[3])
        : "r"(a0), "r"(a1), "r"(a2), "r"(a3), "r"(b0), "r"(b1));
}
__device__ __forceinline__ void ldsm4(uint32_t& r0, uint32_t& r1,
                                      uint32_t& r2, uint32_t& r3, uint32_t addr)
{
    asm volatile("ldmatrix.sync.aligned.m8n8.x4.shared.b16 {%0,%1,%2,%3}, [%4];"
        : "=r"(r0), "=r"(r1), "=r"(r2), "=r"(r3) : "r"(addr));
}
__device__ __forceinline__ void cpa16(uint32_t dst, const void* src) {
    asm volatile("cp.async.cg.shared.global [%0], [%1], 16;" :: "r"(dst), "l"(src));
}
#define CP_COMMIT() asm volatile("cp.async.commit_group;")
#define CP_WAIT0()  asm volatile("cp.async.wait_group 0;")

// ---------------------------------------------------------------------------
// GEMM core (TF32 mma): C[M x 512] = A[M x 512] @ W[512 x 512] + bias.
// ---------------------------------------------------------------------------
__device__ __forceinline__ void gemm_body(
    const float* __restrict__ A, const float* __restrict__ W,
    const float* __restrict__ bias, float* __restrict__ C,
    int round_split, uint32_t* As, uint32_t* Bs)
{
    int tid = threadIdx.x;
    int lane = tid & 31, warp = tid >> 5;
    int wm = (warp >> 2) * 64, wn = (warp & 3) * 32;
    int r = lane >> 2, c = lane & 3;
    int m0 = blockIdx.y * 128, n0 = blockIdx.x * 128;

    float acc[4][4][4];
    #pragma unroll
    for (int im = 0; im < 4; im++)
        #pragma unroll
        for (int in = 0; in < 4; in++)
            #pragma unroll
            for (int q = 0; q < 4; q++) acc[im][in][q] = 0.f;

    for (int k0 = 0; k0 < DD; k0 += 32) {
        #pragma unroll
        for (int l = tid; l < 1024; l += 256) {
            int ar = l >> 3, ac4 = (l & 7) * 4;
            float4 av = *reinterpret_cast<const float4*>(&A[(size_t)(m0 + ar) * DD + k0 + ac4]);
            uint4 au = { f2tf(av.x), f2tf(av.y), f2tf(av.z), f2tf(av.w) };
            *reinterpret_cast<uint4*>(&As[ar * 36 + ac4]) = au;
            int kr = l >> 5, nv = (l & 31) * 4;
            float4 bv = *reinterpret_cast<const float4*>(&W[(size_t)(k0 + kr) * DD + n0 + nv]);
            uint4 bu = { f2tf(bv.x), f2tf(bv.y), f2tf(bv.z), f2tf(bv.w) };
            *reinterpret_cast<uint4*>(&Bs[kr * 136 + nv]) = bu;
        }
        __syncthreads();
        #pragma unroll
        for (int kk = 0; kk < 32; kk += 8) {
            uint32_t a[4][4], b[4][2];
            #pragma unroll
            for (int im = 0; im < 4; im++) {
                int mb = wm + im * 16;
                a[im][0] = As[(mb + r) * 36 + kk + c];
                a[im][1] = As[(mb + r + 8) * 36 + kk + c];
                a[im][2] = As[(mb + r) * 36 + kk + c + 4];
                a[im][3] = As[(mb + r + 8) * 36 + kk + c + 4];
            }
            #pragma unroll
            for (int in = 0; in < 4; in++) {
                int nb = wn + in * 8;
                b[in][0] = Bs[(kk + c) * 136 + nb + r];
                b[in][1] = Bs[(kk + c + 4) * 136 + nb + r];
            }
            #pragma unroll
            for (int im = 0; im < 4; im++)
                #pragma unroll
                for (int in = 0; in < 4; in++)
                    mma8(acc[im][in], a[im][0], a[im][1], a[im][2], a[im][3],
                         b[in][0], b[in][1]);
        }
        __syncthreads();
    }

    #pragma unroll
    for (int im = 0; im < 4; im++) {
        #pragma unroll
        for (int in = 0; in < 4; in++) {
            int row0 = m0 + wm + im * 16 + r;
            int col0 = n0 + wn + in * 8 + 2 * c;
            float bz0 = bias[col0], bz1 = bias[col0 + 1];
            #pragma unroll
            for (int half = 0; half < 2; half++) {
                int row = row0 + half * 8;
                float2 v;
                v.x = acc[im][in][half * 2 + 0] + bz0;
                v.y = acc[im][in][half * 2 + 1] + bz1;
                if (round_split) {
                    v.x = tfr(v.x); v.y = tfr(v.y);
                    int bb = row >> 12, s = row & (SS - 1);
                    int h = col0 >> 6, dk = col0 & 63;
                    *reinterpret_cast<float2*>(
                        &C[(((size_t)(bb * HH + h)) * SS + s) * DK + dk]) = v;
                } else {
                    *reinterpret_cast<float2*>(&C[(size_t)row * DD + col0]) = v;
                }
            }
        }
    }
}

__global__ __launch_bounds__(256) void gemm_qkv(
    const float* __restrict__ Q, const float* __restrict__ K, const float* __restrict__ V,
    const float* __restrict__ wq, const float* __restrict__ wk, const float* __restrict__ wv,
    const float* __restrict__ bq, const float* __restrict__ bk, const float* __restrict__ bv,
    float* __restrict__ cq, float* __restrict__ ck, float* __restrict__ cv)
{
    __shared__ uint32_t As[128 * 36];
    __shared__ uint32_t Bs[32 * 136];
    const float *A, *W, *bias; float* C;
    if (blockIdx.z == 0)      { A = Q; W = wq; bias = bq; C = cq; }
    else if (blockIdx.z == 1) { A = K; W = wk; bias = bk; C = ck; }
    else                      { A = V; W = wv; bias = bv; C = cv; }
    gemm_body(A, W, bias, C, 1, As, Bs);
}

__global__ __launch_bounds__(256) void gemm_out(
    const float* __restrict__ A, const float* __restrict__ W,
    const float* __restrict__ bias, float* __restrict__ C)
{
    __shared__ uint32_t As[128 * 36];
    __shared__ uint32_t Bs[32 * 136];
    gemm_body(A, W, bias, C, 0, As, Bs);
}

// ---------------------------------------------------------------------------
// Split-K single-pass flash attention.
// Flat index f (0..79) decodes (by, chunk, nchunks): nch = by/8 + 1.
// Chunk processes k-tiles [kt0, kt1) of 64 keys; partial (m, l, O) if nch>1.
// smem: Qs[128][68] | K double buf [2][64][68] | V double buf [2][64][72]
// ---------------------------------------------------------------------------
#define FL_SMEM_WORDS (8704 + 2*4352 + 2*4608)   // 26624
#define FL_SMEM_BYTES (FL_SMEM_WORDS * 4)        // 106496
#define K0_OFF 8704
#define K1_OFF 13056
#define V0_OFF 17408
#define V1_OFF 22016

__global__ __launch_bounds__(256, 2) void flash_attn(
    const float* __restrict__ q, const float* __restrict__ k,
    const float* __restrict__ v, float* __restrict__ ctx,
    float* __restrict__ gm, float* __restrict__ glinv,
    float* __restrict__ opart, float* __restrict__ mpart, float* __restrict__ lpart)
{
    extern __shared__ uint32_t smem[];
    uint32_t sb = (uint32_t)__cvta_generic_to_shared(smem);
    int tid = threadIdx.x;
    int lane = tid & 31, wq = tid >> 5;
    int r = lane >> 2, c = lane & 3;
    int ag = lane >> 3, ar = lane & 7;

    // decode (by, ch, nch)
    int f = 79 - (int)blockIdx.x;
    int by, ch, nch;
    if (f < 8)       { by = f;              ch = 0;     nch = 1; }
    else if (f < 24) { int t = f - 8;  by = 8  + (t >> 1); ch = t & 1; nch = 2; }
    else if (f < 48) { int t = f - 24; by = 16 + t / 3;    ch = t % 3; nch = 3; }
    else             { int t = f - 48; by = 24 + (t >> 2); ch = t & 3; nch = 4; }
    int bh = blockIdx.y;
    int ktot = 2 * by + 2;
    int kt0 = ch * ktot / nch;
    int kt1 = (ch + 1) * ktot / nch;
    int nt = kt1 - kt0;

    const float* qb = q + (size_t)bh * SS * DK;
    const float* kb = k + (size_t)bh * SS * DK;
    const float* vb = v + (size_t)bh * SS * DK;

    int i0 = by * 128 + wq * 16 + r, i1 = i0 + 8;

    // ldmatrix lane bases
    uint32_t qaddr = sb + (((wq * 16 + ar + ((ag & 1) << 3)) * 68 + ((ag >> 1) << 2)) << 2);
    uint32_t koff_l = ((((ag >> 1) << 3) + ar) * 68 + ((ag & 1) << 2)) << 2;

    // ---- prologue: Q + first K/V tile via cp.async ----
    #pragma unroll
    for (int l = tid; l < 2048; l += 256) {
        int rr = l >> 4, c4 = (l & 15) * 4;
        cpa16(sb + (rr * 68 + c4) * 4, &qb[(size_t)(by * 128 + rr) * DK + c4]);
    }
    {
        int kt = kt0;
        #pragma unroll
        for (int l = tid; l < 1024; l += 256) {
            int rr = l >> 4, c4 = (l & 15) * 4;
            cpa16(sb + (K0_OFF + rr * 68 + c4) * 4, &kb[(size_t)(kt * 64 + rr) * DK + c4]);
            cpa16(sb + (V0_OFF + rr * 72 + c4) * 4, &vb[(size_t)(kt * 64 + rr) * DK + c4]);
        }
    }
    CP_COMMIT();

    float m0 = -1e30f, m1 = -1e30f, l0 = 0.f, l1 = 0.f;
    float o[8][4];
    #pragma unroll
    for (int n = 0; n < 8; n++)
        #pragma unroll
        for (int qq = 0; qq < 4; qq++) o[n][qq] = 0.f;

    int sq1 = (lane & 28) | (c >> 1);   // shfl src for col x = c
    int sq2 = sq1 + 2;                   // shfl src for col x = c+4
    int comp = c & 1;

    for (int t = 0; t < nt; t++) {
        CP_WAIT0();
        __syncthreads();
        if (t + 1 < nt) {   // prefetch next tile into other buffer
            int kt = kt0 + t + 1;
            int koffs = ((t + 1) & 1) ? K1_OFF : K0_OFF;
            int voffs = ((t + 1) & 1) ? V1_OFF : V0_OFF;
            #pragma unroll
            for (int l = tid; l < 1024; l += 256) {
                int rr = l >> 4, c4 = (l & 15) * 4;
                cpa16(sb + (koffs + rr * 68 + c4) * 4, &kb[(size_t)(kt * 64 + rr) * DK + c4]);
                cpa16(sb + (voffs + rr * 72 + c4) * 4, &vb[(size_t)(kt * 64 + rr) * DK + c4]);
            }
            CP_COMMIT();
        }

        int kt = kt0 + t;
        uint32_t kb_b = sb + ((t & 1) ? K1_OFF : K0_OFF) * 4;
        const uint32_t* Vb = smem + ((t & 1) ? V1_OFF : V0_OFF);

        // ---- S = Q K^T ----
        float s[8][4];
        #pragma unroll
        for (int n = 0; n < 8; n++)
            #pragma unroll
            for (int qq = 0; qq < 4; qq++) s[n][qq] = 0.f;
        #pragma unroll
        for (int kk8 = 0; kk8 < 8; kk8++) {
            uint32_t a0, a1, a2, a3;
            ldsm4(a0, a1, a2, a3, qaddr + kk8 * 32);
            uint32_t b[8][2];
            #pragma unroll
            for (int p = 0; p < 4; p++)
                ldsm4(b[2*p][0], b[2*p][1], b[2*p+1][0], b[2*p+1][1],
                      kb_b + p * 4352 + koff_l + kk8 * 32);
            #pragma unroll
            for (int n = 0; n < 8; n++)
                mma8(s[n], a0, a1, a2, a3, b[n][0], b[n][1]);
        }

        // ---- softmax update (base-2 domain) ----
        bool diag = (kt >= 2 * by);
        float mx0 = -1e30f, mx1 = -1e30f;
        #pragma unroll
        for (int n = 0; n < 8; n++) {
            int j0 = kt * 64 + n * 8 + 2 * c;
            float t0 = s[n][0] * SCL, t1 = s[n][1] * SCL;
            float t2 = s[n][2] * SCL, t3 = s[n][3] * SCL;
            if (diag) {
                if (j0     > i0) t0 = -1e30f;
                if (j0 + 1 > i0) t1 = -1e30f;
                if (j0     > i1) t2 = -1e30f;
                if (j0 + 1 > i1) t3 = -1e30f;
            }
            s[n][0] = t0; s[n][1] = t1; s[n][2] = t2; s[n][3] = t3;
            mx0 = fmaxf(mx0, fmaxf(t0, t1));
            mx1 = fmaxf(mx1, fmaxf(t2, t3));
        }
        mx0 = fmaxf(mx0, __shfl_xor_sync(0xffffffffu, mx0, 1));
        mx0 = fmaxf(mx0, __shfl_xor_sync(0xffffffffu, mx0, 2));
        mx1 = fmaxf(mx1, __shfl_xor_sync(0xffffffffu, mx1, 1));
        mx1 = fmaxf(mx1, __shfl_xor_sync(0xffffffffu, mx1, 2));
        float mn0 = fmaxf(m0, mx0), mn1 = fmaxf(m1, mx1);
        float f0 = ex2(m0 - mn0), f1 = ex2(m1 - mn1);

        uint32_t pt[8][4];
        float sum0 = 0.f, sum1 = 0.f;
        #pragma unroll
        for (int n = 0; n < 8; n++) {
            float p0 = ex2(s[n][0] - mn0);
            float p1 = ex2(s[n][1] - mn0);
            float p2 = ex2(s[n][2] - mn1);
            float p3 = ex2(s[n][3] - mn1);
            sum0 += p0 + p1; sum1 += p2 + p3;
            pt[n][0] = f2tf(p0); pt[n][1] = f2tf(p1);
            pt[n][2] = f2tf(p2); pt[n][3] = f2tf(p3);
        }
        sum0 += __shfl_xor_sync(0xffffffffu, sum0, 1);
        sum0 += __shfl_xor_sync(0xffffffffu, sum0, 2);
        sum1 += __shfl_xor_sync(0xffffffffu, sum1, 1);
        sum1 += __shfl_xor_sync(0xffffffffu, sum1, 2);
        l0 = l0 * f0 + sum0; m0 = mn0;
        l1 = l1 * f1 + sum1; m1 = mn1;

        #pragma unroll
        for (int n = 0; n < 8; n++) {
            o[n][0] *= f0; o[n][1] *= f0;
            o[n][2] *= f1; o[n][3] *= f1;
        }

        // ---- O += P V (P relayout via quad shfls) ----
        #pragma unroll
        for (int g = 0; g < 8; g++) {
            uint32_t v0, v1, a0, a1, a2, a3;
            v0 = __shfl_sync(0xffffffffu, pt[g][0], sq1);
            v1 = __shfl_sync(0xffffffffu, pt[g][1], sq1);
            a0 = comp ? v1 : v0;
            v0 = __shfl_sync(0xffffffffu, pt[g][2], sq1);
            v1 = __shfl_sync(0xffffffffu, pt[g][3], sq1);
            a1 = comp ? v1 : v0;
            v0 = __shfl_sync(0xffffffffu, pt[g][0], sq2);
            v1 = __shfl_sync(0xffffffffu, pt[g][1], sq2);
            a2 = comp ? v1 : v0;
            v0 = __shfl_sync(0xffffffffu, pt[g][2], sq2);
            v1 = __shfl_sync(0xffffffffu, pt[g][3], sq2);
            a3 = comp ? v1 : v0;
            int kk = g * 8;
            #pragma unroll
            for (int n = 0; n < 8; n++) {
                uint32_t b0 = Vb[(kk + c) * 72 + n * 8 + r];
                uint32_t b1 = Vb[(kk + c + 4) * 72 + n * 8 + r];
                mma8(o[n], a0, a1, a2, a3, b0, b1);
            }
        }
    }

    if (nch == 1) {
        float inv0 = 1.0f / l0, inv1 = 1.0f / l1;
        if (c == 0) {
            gm[(size_t)bh * SS + i0] = m0;  glinv[(size_t)bh * SS + i0] = inv0;
            gm[(size_t)bh * SS + i1] = m1;  glinv[(size_t)bh * SS + i1] = inv1;
        }
        int bb = bh >> 3, h = bh & 7;
        #pragma unroll
        for (int n = 0; n < 8; n++) {
            int dk = n * 8 + 2 * c;
            float2 w0 = { o[n][0] * inv0, o[n][1] * inv0 };
            float2 w1 = { o[n][2] * inv1, o[n][3] * inv1 };
            *reinterpret_cast<float2*>(&ctx[((size_t)(bb * SS + i0)) * DD + h * 64 + dk]) = w0;
            *reinterpret_cast<float2*>(&ctx[((size_t)(bb * SS + i1)) * DD + h * 64 + dk]) = w1;
        }
    } else {
        size_t pidx = ((size_t)(bh * 32 + by)) * 4 + ch;
        int lr0 = wq * 16 + r, lr1 = lr0 + 8;
        if (c == 0) {
            mpart[pidx * 128 + lr0] = m0;  lpart[pidx * 128 + lr0] = l0;
            mpart[pidx * 128 + lr1] = m1;  lpart[pidx * 128 + lr1] = l1;
        }
        float* ob = opart + (pidx * 128) * DK;
        #pragma unroll
        for (int n = 0; n < 8; n++) {
            int dk = n * 8 + 2 * c;
            float2 w0 = { o[n][0], o[n][1] };
            float2 w1 = { o[n][2], o[n][3] };
            *reinterpret_cast<float2*>(&ob[(size_t)lr0 * DK + dk]) = w0;
            *reinterpret_cast<float2*>(&ob[(size_t)lr1 * DK + dk]) = w1;
        }
    }
}

// ---------------------------------------------------------------------------
// Combine partial (m, l, O) chunks for by >= 8. One block per (by, bh).
// Thread handles one row-half (32 dk values).
// ---------------------------------------------------------------------------
__global__ __launch_bounds__(256) void flash_combine(
    const float* __restrict__ opart, const float* __restrict__ mpart,
    const float* __restrict__ lpart, float* __restrict__ ctx,
    float* __restrict__ gm, float* __restrict__ glinv)
{
    int by = 8 + blockIdx.x;
    int bh = blockIdx.y;
    int nch = by / 8 + 1;
    int tid = threadIdx.x;
    int row = tid >> 1, half = tid & 1;
    size_t p0 = ((size_t)(bh * 32 + by)) * 4;

    float mf = -1e30f;
    #pragma unroll 4
    for (int chv = 0; chv < 4; chv++)
        if (chv < nch) mf = fmaxf(mf, mpart[(p0 + chv) * 128 + row]);
    float L = 0.f;
    float wch[4];
    #pragma unroll 4
    for (int chv = 0; chv < 4; chv++) {
        if (chv < nch) {
            float w = ex2(mpart[(p0 + chv) * 128 + row] - mf);
            wch[chv] = w;
            L += lpart[(p0 + chv) * 128 + row] * w;
        } else wch[chv] = 0.f;
    }
    float invL = 1.0f / L;

    float acc[32];
    #pragma unroll
    for (int j = 0; j < 32; j++) acc[j] = 0.f;
    #pragma unroll 4
    for (int chv = 0; chv < 4; chv++) {
        if (chv >= nch) break;
        const float* ob = opart + ((p0 + chv) * 128 + row) * DK + half * 32;
        float w = wch[chv];
        #pragma unroll
        for (int j4 = 0; j4 < 8; j4++) {
            float4 vv = *reinterpret_cast<const float4*>(&ob[j4 * 4]);
            acc[j4*4+0] += vv.x * w; acc[j4*4+1] += vv.y * w;
            acc[j4*4+2] += vv.z * w; acc[j4*4+3] += vv.w * w;
        }
    }

    int i = by * 128 + row;
    int bb = bh >> 3, h = bh & 7;
    float* cp = ctx + ((size_t)(bb * SS + i)) * DD + h * 64 + half * 32;
    #pragma unroll
    for (int j4 = 0; j4 < 8; j4++) {
        float4 vv = { acc[j4*4+0] * invL, acc[j4*4+1] * invL,
                      acc[j4*4+2] * invL, acc[j4*4+3] * invL };
        *reinterpret_cast<float4*>(&cp[j4 * 4]) = vv;
    }
    if (half == 0) {
        gm[(size_t)bh * SS + i] = mf;
        glinv[(size_t)bh * SS + i] = invL;
    }
}

// ---------------------------------------------------------------------------
// attn writer: recompute S = Q K^T per 128x128 tile, p = ex2(t-m)*linv.
// ---------------------------------------------------------------------------
#define AW_SMEM_WORDS (8704 * 2)
#define AW_SMEM_BYTES (AW_SMEM_WORDS * 4)

__global__ __launch_bounds__(256, 2) void attn_write(
    const float* __restrict__ q, const float* __restrict__ k,
    const float* __restrict__ gm, const float* __restrict__ glinv,
    float* __restrict__ attn)
{
    int bx = blockIdx.x, by = blockIdx.y, bh = blockIdx.z;
    float* ab = attn + (size_t)bh * SS * SS;
    int tid = threadIdx.x;

    if (bx > by) {  // zero tile
        float4 z = { 0.f, 0.f, 0.f, 0.f };
        #pragma unroll 4
        for (int l = tid; l < 4096; l += 256) {
            int rr = l >> 5, c4 = (l & 31) * 4;
            __stcs(reinterpret_cast<float4*>(
                &ab[(size_t)(by * 128 + rr) * SS + bx * 128 + c4]), z);
        }
        return;
    }

    extern __shared__ uint32_t sm2[];
    uint32_t* Qs = sm2;
    uint32_t* Ks = sm2 + 8704;
    const float* qb = q + (size_t)bh * SS * DK;
    const float* kb = k + (size_t)bh * SS * DK;

    #pragma unroll 4
    for (int l = tid; l < 2048; l += 256) {
        int rr = l >> 4, c4 = (l & 15) * 4;
        *reinterpret_cast<uint4*>(&Qs[rr * 68 + c4]) =
            *reinterpret_cast<const uint4*>(&qb[(size_t)(by * 128 + rr) * DK + c4]);
        *reinterpret_cast<uint4*>(&Ks[rr * 68 + c4]) =
            *reinterpret_cast<const uint4*>(&kb[(size_t)(bx * 128 + rr) * DK + c4]);
    }
    __syncthreads();

    int lane = tid & 31, warp = tid >> 5;
    int wm = (warp >> 2) * 64, wn = (warp & 3) * 32;
    int r = lane >> 2, c = lane & 3;

    float acc[4][4][4];
    #pragma unroll
    for (int im = 0; im < 4; im++)
        #pragma unroll
        for (int in = 0; in < 4; in++)
            #pragma unroll
            for (int qq = 0; qq < 4; qq++) acc[im][in][qq] = 0.f;

    #pragma unroll
    for (int kk = 0; kk < 64; kk += 8) {
        uint32_t a[4][4], b[4][2];
        #pragma unroll
        for (int im = 0; im < 4; im++) {
            int mb = wm + im * 16;
            a[im][0] = Qs[(mb + r) * 68 + kk + c];
            a[im][1] = Qs[(mb + r + 8) * 68 + kk + c];
            a[im][2] = Qs[(mb + r) * 68 + kk + c + 4];
            a[im][3] = Qs[(mb + r + 8) * 68 + kk + c + 4];
        }
        #pragma unroll
        for (int in = 0; in < 4; in++) {
            int nb = wn + in * 8;
            b[in][0] = Ks[(nb + r) * 68 + kk + c];
            b[in][1] = Ks[(nb + r) * 68 + kk + c + 4];
        }
        #pragma unroll
        for (int im = 0; im < 4; im++)
            #pragma unroll
            for (int in = 0; in < 4; in++)
                mma8(acc[im][in], a[im][0], a[im][1], a[im][2], a[im][3],
                     b[in][0], b[in][1]);
    }

    bool dg = (bx == by);
    #pragma unroll
    for (int im = 0; im < 4; im++) {
        int i0 = by * 128 + wm + im * 16 + r;
        int i1 = i0 + 8;
        float m_0 = gm[(size_t)bh * SS + i0], li0 = glinv[(size_t)bh * SS + i0];
        float m_1 = gm[(size_t)bh * SS + i1], li1 = glinv[(size_t)bh * SS + i1];
        #pragma unroll
        for (int in = 0; in < 4; in++) {
            int j0 = bx * 128 + wn + in * 8 + 2 * c;
            float p0 = ex2(acc[im][in][0] * SCL - m_0) * li0;
            float p1 = ex2(acc[im][in][1] * SCL - m_0) * li0;
            float p2 = ex2(acc[im][in][2] * SCL - m_1) * li1;
            float p3 = ex2(acc[im][in][3] * SCL - m_1) * li1;
            if (dg) {
                if (j0     > i0) p0 = 0.f;
                if (j0 + 1 > i0) p1 = 0.f;
                if (j0     > i1) p2 = 0.f;
                if (j0 + 1 > i1) p3 = 0.f;
            }
            float2 w01 = { p0, p1 };
            float2 w23 = { p2, p3 };
            __stcs(reinterpret_cast<float2*>(&ab[(size_t)i0 * SS + j0]), w01);
            __stcs(reinterpret_cast<float2*>(&ab[(size_t)i1 * SS + j0]), w23);
        }
    }
}

// ---------------------------------------------------------------------------
extern "C" void kernel_launch(void* const* d_in, const int* in_sizes, int n_in,
                              void* d_out, int out_size)
{
    (void)in_sizes; (void)n_in;
    const float* Q  = (const float*)d_in[0];
    const float* K  = (const float*)d_in[1];
    const float* V  = (const float*)d_in[2];
    const float* wq = (const float*)d_in[3];
    const float* bq = (const float*)d_in[4];
    const float* wk = (const float*)d_in[5];
    const float* bk = (const float*)d_in[6];
    const float* wv = (const float*)d_in[7];
    const float* bv = (const float*)d_in[8];
    const float* wo = (const float*)d_in[9];
    const float* bo = (const float*)d_in[10];
    float* out = (float*)d_out;

    const size_t outN  = (size_t)MROWS * DD;
    const size_t attnN = (size_t)BH * SS * SS;

    int write_attn;
    float* attn;
    if ((size_t)out_size >= outN + attnN) {
        attn = out + outN;
        write_attn = 1;
    } else {
        void* p = nullptr;
        cudaGetSymbolAddress(&p, g_attn);
        attn = (float*)p;
        write_attn = 0;
    }

    float *qp, *kp, *vp, *ctxp, *mp, *lp, *op, *mpp, *lpp;
    { void* p; cudaGetSymbolAddress(&p, g_q);     qp   = (float*)p; }
    { void* p; cudaGetSymbolAddress(&p, g_k);     kp   = (float*)p; }
    { void* p; cudaGetSymbolAddress(&p, g_v);     vp   = (float*)p; }
    { void* p; cudaGetSymbolAddress(&p, g_ctx);   ctxp = (float*)p; }
    { void* p; cudaGetSymbolAddress(&p, g_m);     mp   = (float*)p; }
    { void* p; cudaGetSymbolAddress(&p, g_linv);  lp   = (float*)p; }
    { void* p; cudaGetSymbolAddress(&p, g_opart); op   = (float*)p; }
    { void* p; cudaGetSymbolAddress(&p, g_mpart); mpp  = (float*)p; }
    { void* p; cudaGetSymbolAddress(&p, g_lpart); lpp  = (float*)p; }

    cudaFuncSetAttribute(flash_attn, cudaFuncAttributeMaxDynamicSharedMemorySize,
                         FL_SMEM_BYTES);
    cudaFuncSetAttribute(attn_write, cudaFuncAttributeMaxDynamicSharedMemorySize,
                         AW_SMEM_BYTES);

    dim3 blk(256);

    dim3 gQKV(DD / 128, MROWS / 128, 3);
    gemm_qkv<<<gQKV, blk>>>(Q, K, V, wq, wk, wv, bq, bk, bv, qp, kp, vp);

    dim3 gFA(80, BH);   // split-K chunks
    flash_attn<<<gFA, blk, FL_SMEM_BYTES>>>(qp, kp, vp, ctxp, mp, lp, op, mpp, lpp);

    dim3 gCB(24, BH);   // by = 8..31 need combining
    flash_combine<<<gCB, blk>>>(op, mpp, lpp, ctxp, mp, lp);

    dim3 gOut(DD / 128, MROWS / 128);
    gemm_out<<<gOut, blk>>>(ctxp, wo, bo, out);

    if (write_attn) {
        dim3 gAW(SS / 128, SS / 128, BH);
        attn_write<<<gAW, blk, AW_SMEM_BYTES>>>(qp, kp, mp, lp, attn);
    }
}

// round 8
// speedup vs baseline: 3.3165x; 1.1189x over previous
#include <cuda_runtime.h>
#include <cuda_bf16.h>
#include <cstdint>

#define BB 2
#define SS 4096
#define DD 512
#define HH 8
#define DK 64
#define BH (BB*HH)          // 16
#define MROWS (BB*SS)       // 8192

// log2(e) * 0.125 (softmax scale folded into base-2 domain)
#define SCL 0.18033688011112042f

// Scratch (device globals: allocation-free)
__device__ float g_q[(size_t)BH * SS * DK];
__device__ float g_k[(size_t)BH * SS * DK];
__device__ float g_v[(size_t)BH * SS * DK];
__device__ float g_ctx[(size_t)MROWS * DD];
__device__ float g_m[(size_t)BH * SS];
__device__ float g_linv[(size_t)BH * SS];
__device__ float g_opart[(size_t)BH * 32 * 4 * 128 * DK];
__device__ float g_mpart[(size_t)BH * 32 * 4 * 128];
__device__ float g_lpart[(size_t)BH * 32 * 4 * 128];
__device__ float g_rin[(size_t)3 * MROWS * DD];     // tf32-rounded Q,K,V inputs
__device__ float g_rw[(size_t)4 * DD * DD];         // tf32-rounded weights
__device__ float g_attn[(size_t)BH * SS * SS];      // used only if attn not in d_out

// ---------------------------------------------------------------------------
__device__ __forceinline__ uint32_t f2tf(float x) {
    uint32_t u;
    asm("cvt.rna.tf32.f32 %0, %1;" : "=r"(u) : "f"(x));
    return u;
}
__device__ __forceinline__ float tfr(float x) {
    return __uint_as_float(f2tf(x));
}
__device__ __forceinline__ float ex2(float x) {
    float y;
    asm("ex2.approx.ftz.f32 %0, %1;" : "=f"(y) : "f"(x));
    return y;
}
__device__ __forceinline__ void mma8(float* d,
    uint32_t a0, uint32_t a1, uint32_t a2, uint32_t a3,
    uint32_t b0, uint32_t b1)
{
    asm volatile(
        "mma.sync.aligned.m16n8k8.row.col.f32.tf32.tf32.f32 "
        "{%0,%1,%2,%3},{%4,%5,%6,%7},{%8,%9},{%0,%1,%2,%3};"
        : "+f"(d[0]), "+f"(d[1]), "+f"(d[2]), "+f"(d[3])
        : "r"(a0), "r"(a1), "r"(a2), "r"(a3), "r"(b0), "r"(b1));
}
__device__ __forceinline__ void ldsm4(uint32_t& r0, uint32_t& r1,
                                      uint32_t& r2, uint32_t& r3, uint32_t addr)
{
    asm volatile("ldmatrix.sync.aligned.m8n8.x4.shared.b16 {%0,%1,%2,%3}, [%4];"
        : "=r"(r0), "=r"(r1), "=r"(r2), "=r"(r3) : "r"(addr));
}
__device__ __forceinline__ void cpa16(uint32_t dst, const void* src) {
    asm volatile("cp.async.cg.shared.global [%0], [%1], 16;" :: "r"(dst), "l"(src));
}
#define CP_COMMIT() asm volatile("cp.async.commit_group;")
#define CP_WAIT0()  asm volatile("cp.async.wait_group 0;")

// ---------------------------------------------------------------------------
// Prepass: tf32-round Q,K,V inputs and the 4 weight matrices into scratch.
// ---------------------------------------------------------------------------
#define NINW ((size_t)3 * MROWS * DD)    // 12,582,912 floats
#define NWW  ((size_t)4 * DD * DD)       // 1,048,576 floats

__global__ __launch_bounds__(256) void round_pre(
    const float* __restrict__ Q, const float* __restrict__ K, const float* __restrict__ V,
    const float* __restrict__ wq, const float* __restrict__ wk,
    const float* __restrict__ wv, const float* __restrict__ wo,
    float* __restrict__ rin, float* __restrict__ rw)
{
    size_t idx = ((size_t)blockIdx.x * 256 + threadIdx.x) * 4;
    const size_t NPER = (size_t)MROWS * DD;   // 4,194,304
    if (idx < NINW) {
        const float* src = (idx < NPER) ? Q : (idx < 2 * NPER ? K : V);
        size_t off = idx & (NPER - 1);
        float4 v = *reinterpret_cast<const float4*>(&src[off]);
        float4 o = { tfr(v.x), tfr(v.y), tfr(v.z), tfr(v.w) };
        *reinterpret_cast<float4*>(&rin[idx]) = o;
    } else {
        size_t j = idx - NINW;
        const size_t WPER = (size_t)DD * DD;  // 262,144
        const float* src = (j < WPER) ? wq : (j < 2 * WPER ? wk : (j < 3 * WPER ? wv : wo));
        size_t off = j & (WPER - 1);
        float4 v = *reinterpret_cast<const float4*>(&src[off]);
        float4 o = { tfr(v.x), tfr(v.y), tfr(v.z), tfr(v.w) };
        *reinterpret_cast<float4*>(&rw[j]) = o;
    }
}

// ---------------------------------------------------------------------------
// Double-buffered TF32 GEMM: C[M x 512] = A[M x 512] @ W[512 x 512] + bias.
// A and W must be pre-rounded to tf32. cp.async pipeline, 1 sync per k-chunk.
// smem (dynamic): A0[128*36] A1 | B0[32*136] B1  = 17920 words
// ---------------------------------------------------------------------------
#define GQ_A0 0
#define GQ_A1 4608
#define GQ_B0 9216
#define GQ_B1 13568
#define GEMM_SMEM_BYTES (17920 * 4)   // 71680

__device__ __forceinline__ void gemm_body_db(
    const float* __restrict__ A, const float* __restrict__ W,
    const float* __restrict__ bias, float* __restrict__ C,
    int round_split, uint32_t* sm)
{
    uint32_t sb = (uint32_t)__cvta_generic_to_shared(sm);
    int tid = threadIdx.x;
    int lane = tid & 31, warp = tid >> 5;
    int wm = (warp >> 2) * 64, wn = (warp & 3) * 32;
    int r = lane >> 2, c = lane & 3;
    int ag = lane >> 3, ar = lane & 7;
    int m0 = blockIdx.y * 128, n0 = blockIdx.x * 128;
    uint32_t a_lane = ((uint32_t)((ar + ((ag & 1) << 3)) * 36 + ((ag >> 1) << 2))) << 2;

    float acc[4][4][4] = {};

    // prologue: chunk 0
    #pragma unroll
    for (int it = 0; it < 4; it++) {
        int l = tid + it * 256;
        int arow = l >> 3, ac4 = (l & 7) * 4;
        cpa16(sb + (uint32_t)((GQ_A0 + arow * 36 + ac4) * 4),
              &A[(size_t)(m0 + arow) * DD + ac4]);
        int kr = l >> 5, nv = (l & 31) * 4;
        cpa16(sb + (uint32_t)((GQ_B0 + kr * 136 + nv) * 4),
              &W[(size_t)kr * DD + n0 + nv]);
    }
    CP_COMMIT();

    for (int kc = 0; kc < 16; kc++) {
        CP_WAIT0();
        __syncthreads();
        if (kc < 15) {
            int k0n = (kc + 1) * 32;
            int ao = ((kc + 1) & 1) ? GQ_A1 : GQ_A0;
            int bo = ((kc + 1) & 1) ? GQ_B1 : GQ_B0;
            #pragma unroll
            for (int it = 0; it < 4; it++) {
                int l = tid + it * 256;
                int arow = l >> 3, ac4 = (l & 7) * 4;
                cpa16(sb + (uint32_t)((ao + arow * 36 + ac4) * 4),
                      &A[(size_t)(m0 + arow) * DD + k0n + ac4]);
                int kr = l >> 5, nv = (l & 31) * 4;
                cpa16(sb + (uint32_t)((bo + kr * 136 + nv) * 4),
                      &W[(size_t)(k0n + kr) * DD + n0 + nv]);
            }
            CP_COMMIT();
        }
        uint32_t ab_s = sb + (uint32_t)((((kc & 1) ? GQ_A1 : GQ_A0)) * 4);
        const uint32_t* Bb = sm + ((kc & 1) ? GQ_B1 : GQ_B0);
        #pragma unroll
        for (int kk = 0; kk < 32; kk += 8) {
            uint32_t a[4][4], b[4][2];
            #pragma unroll
            for (int im = 0; im < 4; im++)
                ldsm4(a[im][0], a[im][1], a[im][2], a[im][3],
                      ab_s + (uint32_t)(((wm + im * 16) * 36 + kk) * 4) + a_lane);
            #pragma unroll
            for (int in = 0; in < 4; in++) {
                int nb = wn + in * 8;
                b[in][0] = Bb[(kk + c) * 136 + nb + r];
                b[in][1] = Bb[(kk + c + 4) * 136 + nb + r];
            }
            #pragma unroll
            for (int im = 0; im < 4; im++)
                #pragma unroll
                for (int in = 0; in < 4; in++)
                    mma8(acc[im][in], a[im][0], a[im][1], a[im][2], a[im][3],
                         b[in][0], b[in][1]);
        }
    }

    #pragma unroll
    for (int im = 0; im < 4; im++) {
        #pragma unroll
        for (int in = 0; in < 4; in++) {
            int row0 = m0 + wm + im * 16 + r;
            int col0 = n0 + wn + in * 8 + 2 * c;
            float bz0 = bias[col0], bz1 = bias[col0 + 1];
            #pragma unroll
            for (int half = 0; half < 2; half++) {
                int row = row0 + half * 8;
                float2 v;
                v.x = acc[im][in][half * 2 + 0] + bz0;
                v.y = acc[im][in][half * 2 + 1] + bz1;
                if (round_split) {
                    v.x = tfr(v.x); v.y = tfr(v.y);
                    int bb = row >> 12, s = row & (SS - 1);
                    int h = col0 >> 6, dk = col0 & 63;
                    *reinterpret_cast<float2*>(
                        &C[(((size_t)(bb * HH + h)) * SS + s) * DK + dk]) = v;
                } else {
                    *reinterpret_cast<float2*>(&C[(size_t)row * DD + col0]) = v;
                }
            }
        }
    }
}

__global__ __launch_bounds__(256, 2) void gemm_qkv(
    const float* __restrict__ rin, const float* __restrict__ rw,
    const float* __restrict__ bq, const float* __restrict__ bk, const float* __restrict__ bv,
    float* __restrict__ cq, float* __restrict__ ck, float* __restrict__ cv)
{
    extern __shared__ uint32_t dsm[];
    int z = blockIdx.z;
    const float* A = rin + (size_t)z * MROWS * DD;
    const float* W = rw + (size_t)z * DD * DD;
    const float* bias = (z == 0) ? bq : (z == 1 ? bk : bv);
    float* C = (z == 0) ? cq : (z == 1 ? ck : cv);
    gemm_body_db(A, W, bias, C, 1, dsm);
}

__global__ __launch_bounds__(256, 2) void gemm_out(
    const float* __restrict__ A, const float* __restrict__ rw,
    const float* __restrict__ bias, float* __restrict__ C)
{
    extern __shared__ uint32_t dsm[];
    gemm_body_db(A, rw + (size_t)3 * DD * DD, bias, C, 0, dsm);
}

// ---------------------------------------------------------------------------
// Split-K single-pass flash attention (unchanged structure; ctx now tf32-rounded).
// ---------------------------------------------------------------------------
#define FL_SMEM_WORDS (8704 + 2*4352 + 2*4608)
#define FL_SMEM_BYTES (FL_SMEM_WORDS * 4)
#define K0_OFF 8704
#define K1_OFF 13056
#define V0_OFF 17408
#define V1_OFF 22016

__global__ __launch_bounds__(256, 2) void flash_attn(
    const float* __restrict__ q, const float* __restrict__ k,
    const float* __restrict__ v, float* __restrict__ ctx,
    float* __restrict__ gm, float* __restrict__ glinv,
    float* __restrict__ opart, float* __restrict__ mpart, float* __restrict__ lpart)
{
    extern __shared__ uint32_t smem[];
    uint32_t sb = (uint32_t)__cvta_generic_to_shared(smem);
    int tid = threadIdx.x;
    int lane = tid & 31, wq = tid >> 5;
    int r = lane >> 2, c = lane & 3;
    int ag = lane >> 3, ar = lane & 7;

    int f = 79 - (int)blockIdx.x;
    int by, ch, nch;
    if (f < 8)       { by = f;              ch = 0;     nch = 1; }
    else if (f < 24) { int t = f - 8;  by = 8  + (t >> 1); ch = t & 1; nch = 2; }
    else if (f < 48) { int t = f - 24; by = 16 + t / 3;    ch = t % 3; nch = 3; }
    else             { int t = f - 48; by = 24 + (t >> 2); ch = t & 3; nch = 4; }
    int bh = blockIdx.y;
    int ktot = 2 * by + 2;
    int kt0 = ch * ktot / nch;
    int kt1 = (ch + 1) * ktot / nch;
    int nt = kt1 - kt0;

    const float* qb = q + (size_t)bh * SS * DK;
    const float* kb = k + (size_t)bh * SS * DK;
    const float* vb = v + (size_t)bh * SS * DK;

    int i0 = by * 128 + wq * 16 + r, i1 = i0 + 8;

    uint32_t qaddr = sb + (((wq * 16 + ar + ((ag & 1) << 3)) * 68 + ((ag >> 1) << 2)) << 2);
    uint32_t koff_l = ((((ag >> 1) << 3) + ar) * 68 + ((ag & 1) << 2)) << 2;

    #pragma unroll
    for (int l = tid; l < 2048; l += 256) {
        int rr = l >> 4, c4 = (l & 15) * 4;
        cpa16(sb + (rr * 68 + c4) * 4, &qb[(size_t)(by * 128 + rr) * DK + c4]);
    }
    {
        int kt = kt0;
        #pragma unroll
        for (int l = tid; l < 1024; l += 256) {
            int rr = l >> 4, c4 = (l & 15) * 4;
            cpa16(sb + (K0_OFF + rr * 68 + c4) * 4, &kb[(size_t)(kt * 64 + rr) * DK + c4]);
            cpa16(sb + (V0_OFF + rr * 72 + c4) * 4, &vb[(size_t)(kt * 64 + rr) * DK + c4]);
        }
    }
    CP_COMMIT();

    float m0 = -1e30f, m1 = -1e30f, l0 = 0.f, l1 = 0.f;
    float o[8][4];
    #pragma unroll
    for (int n = 0; n < 8; n++)
        #pragma unroll
        for (int qq = 0; qq < 4; qq++) o[n][qq] = 0.f;

    int sq1 = (lane & 28) | (c >> 1);
    int sq2 = sq1 + 2;
    int comp = c & 1;

    for (int t = 0; t < nt; t++) {
        CP_WAIT0();
        __syncthreads();
        if (t + 1 < nt) {
            int kt = kt0 + t + 1;
            int koffs = ((t + 1) & 1) ? K1_OFF : K0_OFF;
            int voffs = ((t + 1) & 1) ? V1_OFF : V0_OFF;
            #pragma unroll
            for (int l = tid; l < 1024; l += 256) {
                int rr = l >> 4, c4 = (l & 15) * 4;
                cpa16(sb + (koffs + rr * 68 + c4) * 4, &kb[(size_t)(kt * 64 + rr) * DK + c4]);
                cpa16(sb + (voffs + rr * 72 + c4) * 4, &vb[(size_t)(kt * 64 + rr) * DK + c4]);
            }
            CP_COMMIT();
        }

        int kt = kt0 + t;
        uint32_t kb_b = sb + ((t & 1) ? K1_OFF : K0_OFF) * 4;
        const uint32_t* Vb = smem + ((t & 1) ? V1_OFF : V0_OFF);

        float s[8][4];
        #pragma unroll
        for (int n = 0; n < 8; n++)
            #pragma unroll
            for (int qq = 0; qq < 4; qq++) s[n][qq] = 0.f;
        #pragma unroll
        for (int kk8 = 0; kk8 < 8; kk8++) {
            uint32_t a0, a1, a2, a3;
            ldsm4(a0, a1, a2, a3, qaddr + kk8 * 32);
            uint32_t b[8][2];
            #pragma unroll
            for (int p = 0; p < 4; p++)
                ldsm4(b[2*p][0], b[2*p][1], b[2*p+1][0], b[2*p+1][1],
                      kb_b + p * 4352 + koff_l + kk8 * 32);
            #pragma unroll
            for (int n = 0; n < 8; n++)
                mma8(s[n], a0, a1, a2, a3, b[n][0], b[n][1]);
        }

        bool diag = (kt >= 2 * by);
        float mx0 = -1e30f, mx1 = -1e30f;
        #pragma unroll
        for (int n = 0; n < 8; n++) {
            int j0 = kt * 64 + n * 8 + 2 * c;
            float t0 = s[n][0] * SCL, t1 = s[n][1] * SCL;
            float t2 = s[n][2] * SCL, t3 = s[n][3] * SCL;
            if (diag) {
                if (j0     > i0) t0 = -1e30f;
                if (j0 + 1 > i0) t1 = -1e30f;
                if (j0     > i1) t2 = -1e30f;
                if (j0 + 1 > i1) t3 = -1e30f;
            }
            s[n][0] = t0; s[n][1] = t1; s[n][2] = t2; s[n][3] = t3;
            mx0 = fmaxf(mx0, fmaxf(t0, t1));
            mx1 = fmaxf(mx1, fmaxf(t2, t3));
        }
        mx0 = fmaxf(mx0, __shfl_xor_sync(0xffffffffu, mx0, 1));
        mx0 = fmaxf(mx0, __shfl_xor_sync(0xffffffffu, mx0, 2));
        mx1 = fmaxf(mx1, __shfl_xor_sync(0xffffffffu, mx1, 1));
        mx1 = fmaxf(mx1, __shfl_xor_sync(0xffffffffu, mx1, 2));
        float mn0 = fmaxf(m0, mx0), mn1 = fmaxf(m1, mx1);
        float f0 = ex2(m0 - mn0), f1 = ex2(m1 - mn1);

        uint32_t pt[8][4];
        float sum0 = 0.f, sum1 = 0.f;
        #pragma unroll
        for (int n = 0; n < 8; n++) {
            float p0 = ex2(s[n][0] - mn0);
            float p1 = ex2(s[n][1] - mn0);
            float p2 = ex2(s[n][2] - mn1);
            float p3 = ex2(s[n][3] - mn1);
            sum0 += p0 + p1; sum1 += p2 + p3;
            pt[n][0] = f2tf(p0); pt[n][1] = f2tf(p1);
            pt[n][2] = f2tf(p2); pt[n][3] = f2tf(p3);
        }
        sum0 += __shfl_xor_sync(0xffffffffu, sum0, 1);
        sum0 += __shfl_xor_sync(0xffffffffu, sum0, 2);
        sum1 += __shfl_xor_sync(0xffffffffu, sum1, 1);
        sum1 += __shfl_xor_sync(0xffffffffu, sum1, 2);
        l0 = l0 * f0 + sum0; m0 = mn0;
        l1 = l1 * f1 + sum1; m1 = mn1;

        #pragma unroll
        for (int n = 0; n < 8; n++) {
            o[n][0] *= f0; o[n][1] *= f0;
            o[n][2] *= f1; o[n][3] *= f1;
        }

        #pragma unroll
        for (int g = 0; g < 8; g++) {
            uint32_t v0, v1, a0, a1, a2, a3;
            v0 = __shfl_sync(0xffffffffu, pt[g][0], sq1);
            v1 = __shfl_sync(0xffffffffu, pt[g][1], sq1);
            a0 = comp ? v1 : v0;
            v0 = __shfl_sync(0xffffffffu, pt[g][2], sq1);
            v1 = __shfl_sync(0xffffffffu, pt[g][3], sq1);
            a1 = comp ? v1 : v0;
            v0 = __shfl_sync(0xffffffffu, pt[g][0], sq2);
            v1 = __shfl_sync(0xffffffffu, pt[g][1], sq2);
            a2 = comp ? v1 : v0;
            v0 = __shfl_sync(0xffffffffu, pt[g][2], sq2);
            v1 = __shfl_sync(0xffffffffu, pt[g][3], sq2);
            a3 = comp ? v1 : v0;
            int kk = g * 8;
            #pragma unroll
            for (int n = 0; n < 8; n++) {
                uint32_t b0 = Vb[(kk + c) * 72 + n * 8 + r];
                uint32_t b1 = Vb[(kk + c + 4) * 72 + n * 8 + r];
                mma8(o[n], a0, a1, a2, a3, b0, b1);
            }
        }
    }

    if (nch == 1) {
        float inv0 = 1.0f / l0, inv1 = 1.0f / l1;
        if (c == 0) {
            gm[(size_t)bh * SS + i0] = m0;  glinv[(size_t)bh * SS + i0] = inv0;
            gm[(size_t)bh * SS + i1] = m1;  glinv[(size_t)bh * SS + i1] = inv1;
        }
        int bb = bh >> 3, h = bh & 7;
        #pragma unroll
        for (int n = 0; n < 8; n++) {
            int dk = n * 8 + 2 * c;
            float2 w0 = { tfr(o[n][0] * inv0), tfr(o[n][1] * inv0) };
            float2 w1 = { tfr(o[n][2] * inv1), tfr(o[n][3] * inv1) };
            *reinterpret_cast<float2*>(&ctx[((size_t)(bb * SS + i0)) * DD + h * 64 + dk]) = w0;
            *reinterpret_cast<float2*>(&ctx[((size_t)(bb * SS + i1)) * DD + h * 64 + dk]) = w1;
        }
    } else {
        size_t pidx = ((size_t)(bh * 32 + by)) * 4 + ch;
        int lr0 = wq * 16 + r, lr1 = lr0 + 8;
        if (c == 0) {
            mpart[pidx * 128 + lr0] = m0;  lpart[pidx * 128 + lr0] = l0;
            mpart[pidx * 128 + lr1] = m1;  lpart[pidx * 128 + lr1] = l1;
        }
        float* ob = opart + (pidx * 128) * DK;
        #pragma unroll
        for (int n = 0; n < 8; n++) {
            int dk = n * 8 + 2 * c;
            float2 w0 = { o[n][0], o[n][1] };
            float2 w1 = { o[n][2], o[n][3] };
            *reinterpret_cast<float2*>(&ob[(size_t)lr0 * DK + dk]) = w0;
            *reinterpret_cast<float2*>(&ob[(size_t)lr1 * DK + dk]) = w1;
        }
    }
}

// ---------------------------------------------------------------------------
// Combine partial (m, l, O) chunks for by >= 8. ctx output tf32-rounded.
// ---------------------------------------------------------------------------
__global__ __launch_bounds__(256) void flash_combine(
    const float* __restrict__ opart, const float* __restrict__ mpart,
    const float* __restrict__ lpart, float* __restrict__ ctx,
    float* __restrict__ gm, float* __restrict__ glinv)
{
    int by = 8 + blockIdx.x;
    int bh = blockIdx.y;
    int nch = by / 8 + 1;
    int tid = threadIdx.x;
    int row = tid >> 1, half = tid & 1;
    size_t p0 = ((size_t)(bh * 32 + by)) * 4;

    float mf = -1e30f;
    #pragma unroll 4
    for (int chv = 0; chv < 4; chv++)
        if (chv < nch) mf = fmaxf(mf, mpart[(p0 + chv) * 128 + row]);
    float L = 0.f;
    float wch[4];
    #pragma unroll 4
    for (int chv = 0; chv < 4; chv++) {
        if (chv < nch) {
            float w = ex2(mpart[(p0 + chv) * 128 + row] - mf);
            wch[chv] = w;
            L += lpart[(p0 + chv) * 128 + row] * w;
        } else wch[chv] = 0.f;
    }
    float invL = 1.0f / L;

    float acc[32];
    #pragma unroll
    for (int j = 0; j < 32; j++) acc[j] = 0.f;
    #pragma unroll 4
    for (int chv = 0; chv < 4; chv++) {
        if (chv >= nch) break;
        const float* ob = opart + ((p0 + chv) * 128 + row) * DK + half * 32;
        float w = wch[chv];
        #pragma unroll
        for (int j4 = 0; j4 < 8; j4++) {
            float4 vv = *reinterpret_cast<const float4*>(&ob[j4 * 4]);
            acc[j4*4+0] += vv.x * w; acc[j4*4+1] += vv.y * w;
            acc[j4*4+2] += vv.z * w; acc[j4*4+3] += vv.w * w;
        }
    }

    int i = by * 128 + row;
    int bb = bh >> 3, h = bh & 7;
    float* cp = ctx + ((size_t)(bb * SS + i)) * DD + h * 64 + half * 32;
    #pragma unroll
    for (int j4 = 0; j4 < 8; j4++) {
        float4 vv = { tfr(acc[j4*4+0] * invL), tfr(acc[j4*4+1] * invL),
                      tfr(acc[j4*4+2] * invL), tfr(acc[j4*4+3] * invL) };
        *reinterpret_cast<float4*>(&cp[j4 * 4]) = vv;
    }
    if (half == 0) {
        gm[(size_t)bh * SS + i] = mf;
        glinv[(size_t)bh * SS + i] = invL;
    }
}

// ---------------------------------------------------------------------------
// attn writer: recompute S, p = ex2(t-m)*linv, stage in smem, coalesced stores.
// smem reused: Qs[128*68] + Ks[128*68] = 17408 words = Ps[128][136] floats.
// ---------------------------------------------------------------------------
#define AW_SMEM_WORDS (8704 * 2)
#define AW_SMEM_BYTES (AW_SMEM_WORDS * 4)

__global__ __launch_bounds__(256, 2) void attn_write(
    const float* __restrict__ q, const float* __restrict__ k,
    const float* __restrict__ gm, const float* __restrict__ glinv,
    float* __restrict__ attn)
{
    int bx = blockIdx.x, by = blockIdx.y, bh = blockIdx.z;
    float* ab = attn + (size_t)bh * SS * SS;
    int tid = threadIdx.x;

    if (bx > by) {  // zero tile
        float4 z = { 0.f, 0.f, 0.f, 0.f };
        #pragma unroll 4
        for (int l = tid; l < 4096; l += 256) {
            int rr = l >> 5, c4 = (l & 31) * 4;
            __stcs(reinterpret_cast<float4*>(
                &ab[(size_t)(by * 128 + rr) * SS + bx * 128 + c4]), z);
        }
        return;
    }

    extern __shared__ uint32_t sm2[];
    uint32_t* Qs = sm2;
    uint32_t* Ks = sm2 + 8704;
    const float* qb = q + (size_t)bh * SS * DK;
    const float* kb = k + (size_t)bh * SS * DK;

    #pragma unroll 4
    for (int l = tid; l < 2048; l += 256) {
        int rr = l >> 4, c4 = (l & 15) * 4;
        *reinterpret_cast<uint4*>(&Qs[rr * 68 + c4]) =
            *reinterpret_cast<const uint4*>(&qb[(size_t)(by * 128 + rr) * DK + c4]);
        *reinterpret_cast<uint4*>(&Ks[rr * 68 + c4]) =
            *reinterpret_cast<const uint4*>(&kb[(size_t)(bx * 128 + rr) * DK + c4]);
    }
    __syncthreads();

    int lane = tid & 31, warp = tid >> 5;
    int wm = (warp >> 2) * 64, wn = (warp & 3) * 32;
    int r = lane >> 2, c = lane & 3;

    float acc[4][4][4];
    #pragma unroll
    for (int im = 0; im < 4; im++)
        #pragma unroll
        for (int in = 0; in < 4; in++)
            #pragma unroll
            for (int qq = 0; qq < 4; qq++) acc[im][in][qq] = 0.f;

    #pragma unroll
    for (int kk = 0; kk < 64; kk += 8) {
        uint32_t a[4][4], b[4][2];
        #pragma unroll
        for (int im = 0; im < 4; im++) {
            int mb = wm + im * 16;
            a[im][0] = Qs[(mb + r) * 68 + kk + c];
            a[im][1] = Qs[(mb + r + 8) * 68 + kk + c];
            a[im][2] = Qs[(mb + r) * 68 + kk + c + 4];
            a[im][3] = Qs[(mb + r + 8) * 68 + kk + c + 4];
        }
        #pragma unroll
        for (int in = 0; in < 4; in++) {
            int nb = wn + in * 8;
            b[in][0] = Ks[(nb + r) * 68 + kk + c];
            b[in][1] = Ks[(nb + r) * 68 + kk + c + 4];
        }
        #pragma unroll
        for (int im = 0; im < 4; im++)
            #pragma unroll
            for (int in = 0; in < 4; in++)
                mma8(acc[im][in], a[im][0], a[im][1], a[im][2], a[im][3],
                     b[in][0], b[in][1]);
    }

    // stage normalized P into smem (stride 136: conflict-free STS + LDS)
    __syncthreads();  // everyone done reading Qs/Ks
    float* Ps = reinterpret_cast<float*>(sm2);
    bool dg = (bx == by);
    #pragma unroll
    for (int im = 0; im < 4; im++) {
        int i0 = by * 128 + wm + im * 16 + r;
        int i1 = i0 + 8;
        int lr0 = wm + im * 16 + r, lr1 = lr0 + 8;
        float m_0 = gm[(size_t)bh * SS + i0], li0 = glinv[(size_t)bh * SS + i0];
        float m_1 = gm[(size_t)bh * SS + i1], li1 = glinv[(size_t)bh * SS + i1];
        #pragma unroll
        for (int in = 0; in < 4; in++) {
            int j = wn + in * 8 + 2 * c;
            int j0 = bx * 128 + j;
            float p0 = ex2(acc[im][in][0] * SCL - m_0) * li0;
            float p1 = ex2(acc[im][in][1] * SCL - m_0) * li0;
            float p2 = ex2(acc[im][in][2] * SCL - m_1) * li1;
            float p3 = ex2(acc[im][in][3] * SCL - m_1) * li1;
            if (dg) {
                if (j0     > i0) p0 = 0.f;
                if (j0 + 1 > i0) p1 = 0.f;
                if (j0     > i1) p2 = 0.f;
                if (j0 + 1 > i1) p3 = 0.f;
            }
            float2 w01 = { p0, p1 };
            float2 w23 = { p2, p3 };
            *reinterpret_cast<float2*>(&Ps[lr0 * 136 + j]) = w01;
            *reinterpret_cast<float2*>(&Ps[lr1 * 136 + j]) = w23;
        }
    }
    __syncthreads();

    // coalesced streaming writes: 512B per warp-row
    #pragma unroll 4
    for (int l = tid; l < 4096; l += 256) {
        int rr = l >> 5, c4 = (l & 31) * 4;
        float4 vv = *reinterpret_cast<const float4*>(&Ps[rr * 136 + c4]);
        __stcs(reinterpret_cast<float4*>(
            &ab[(size_t)(by * 128 + rr) * SS + bx * 128 + c4]), vv);
    }
}

// ---------------------------------------------------------------------------
extern "C" void kernel_launch(void* const* d_in, const int* in_sizes, int n_in,
                              void* d_out, int out_size)
{
    (void)in_sizes; (void)n_in;
    const float* Q  = (const float*)d_in[0];
    const float* K  = (const float*)d_in[1];
    const float* V  = (const float*)d_in[2];
    const float* wq = (const float*)d_in[3];
    const float* bq = (const float*)d_in[4];
    const float* wk = (const float*)d_in[5];
    const float* bk = (const float*)d_in[6];
    const float* wv = (const float*)d_in[7];
    const float* bv = (const float*)d_in[8];
    const float* wo = (const float*)d_in[9];
    const float* bo = (const float*)d_in[10];
    float* out = (float*)d_out;

    const size_t outN  = (size_t)MROWS * DD;
    const size_t attnN = (size_t)BH * SS * SS;

    int write_attn;
    float* attn;
    if ((size_t)out_size >= outN + attnN) {
        attn = out + outN;
        write_attn = 1;
    } else {
        void* p = nullptr;
        cudaGetSymbolAddress(&p, g_attn);
        attn = (float*)p;
        write_attn = 0;
    }

    float *qp, *kp, *vp, *ctxp, *mp, *lp, *op, *mpp, *lpp, *rin, *rw;
    { void* p; cudaGetSymbolAddress(&p, g_q);     qp   = (float*)p; }
    { void* p; cudaGetSymbolAddress(&p, g_k);     kp   = (float*)p; }
    { void* p; cudaGetSymbolAddress(&p, g_v);     vp   = (float*)p; }
    { void* p; cudaGetSymbolAddress(&p, g_ctx);   ctxp = (float*)p; }
    { void* p; cudaGetSymbolAddress(&p, g_m);     mp   = (float*)p; }
    { void* p; cudaGetSymbolAddress(&p, g_linv);  lp   = (float*)p; }
    { void* p; cudaGetSymbolAddress(&p, g_opart); op   = (float*)p; }
    { void* p; cudaGetSymbolAddress(&p, g_mpart); mpp  = (float*)p; }
    { void* p; cudaGetSymbolAddress(&p, g_lpart); lpp  = (float*)p; }
    { void* p; cudaGetSymbolAddress(&p, g_rin);   rin  = (float*)p; }
    { void* p; cudaGetSymbolAddress(&p, g_rw);    rw   = (float*)p; }

    cudaFuncSetAttribute(flash_attn, cudaFuncAttributeMaxDynamicSharedMemorySize,
                         FL_SMEM_BYTES);
    cudaFuncSetAttribute(attn_write, cudaFuncAttributeMaxDynamicSharedMemorySize,
                         AW_SMEM_BYTES);
    cudaFuncSetAttribute(gemm_qkv, cudaFuncAttributeMaxDynamicSharedMemorySize,
                         GEMM_SMEM_BYTES);
    cudaFuncSetAttribute(gemm_out, cudaFuncAttributeMaxDynamicSharedMemorySize,
                         GEMM_SMEM_BYTES);

    dim3 blk(256);

    // prepass: tf32-round Q,K,V inputs + weights
    size_t totalRound = (NINW + NWW) / 4;           // float4 count
    round_pre<<<(unsigned)(totalRound / 256), blk>>>(Q, K, V, wq, wk, wv, wo, rin, rw);

    dim3 gQKV(DD / 128, MROWS / 128, 3);
    gemm_qkv<<<gQKV, blk, GEMM_SMEM_BYTES>>>(rin, rw, bq, bk, bv, qp, kp, vp);

    dim3 gFA(80, BH);
    flash_attn<<<gFA, blk, FL_SMEM_BYTES>>>(qp, kp, vp, ctxp, mp, lp, op, mpp, lpp);

    dim3 gCB(24, BH);
    flash_combine<<<gCB, blk>>>(op, mpp, lpp, ctxp, mp, lp);

    dim3 gOut(DD / 128, MROWS / 128);
    gemm_out<<<gOut, blk, GEMM_SMEM_BYTES>>>(ctxp, rw, bo, out);

    if (write_attn) {
        dim3 gAW(SS / 128, SS / 128, BH);
        attn_write<<<gAW, blk, AW_SMEM_BYTES>>>(qp, kp, mp, lp, attn);
    }
}